// round 1
// baseline (speedup 1.0000x reference)
#include <cuda_runtime.h>
#include <math.h>

// Problem constants
#define NB 2
#define NC 4
#define NL 1024
#define NF 256
#define NH 8
#define ND 32
#define NN (NB*NL)          // 2048 samples
#define NBH (NB*NC*NH)      // 64 attention slices
#define HOUT_SIZE (NB*NC*NL*NF)  // 2097152

#define SAS 68  // padded smem stride for transposed tiles (multiple of 4, conflict-spreading)

// ------------------- scratch (static device memory; no allocs) -------------------
__device__ float g_conv[3 * NC * NN * NF];  // conv outputs for q,k,v  (24 MB)
__device__ float g_qh[NBH * NL * ND];       // rotated+scaled Q heads  (8 MB)
__device__ float g_kh[NBH * NL * ND];       // rotated K heads
__device__ float g_vh[NBH * NL * ND];       // V heads
__device__ float g_a [NC * NN * NF];        // attention output, [c][n][f]
__device__ float g_o [NC * NN * NF];        // wo output, [c][n][f]

// =================================================================================
// Kernel 1: instance-norm (per n, per channel over 256) + 3-tap conv -> g_conv
// =================================================================================
__global__ void __launch_bounds__(256) k_norm_conv(
    const float* __restrict__ x,
    const float* __restrict__ g1, const float* __restrict__ b1,
    const float* __restrict__ wq, const float* __restrict__ wk, const float* __restrict__ wv)
{
    __shared__ float snx[4][256];
    __shared__ float sw[3][4][4][3];   // [mat][o][i][kh]
    __shared__ float sredA[8], sredB[8];
    __shared__ float sbc[2];

    int f = threadIdx.x;
    int n = blockIdx.x;
    int b = n >> 10, l = n & 1023;

    if (f < 144) {
        int mat = f / 48, rem = f % 48;
        int o = rem / 12, i = (rem % 12) / 3, kh = rem % 3;
        const float* wsrc = (mat == 0) ? wq : (mat == 1) ? wk : wv;
        sw[mat][o][i][kh] = wsrc[(o*4 + i)*9 + kh*3 + 1];  // kw=1 slice only (W=1)
    }

    float xv[4];
    #pragma unroll
    for (int c = 0; c < 4; c++)
        xv[c] = x[((size_t)(b*4 + c)*1024 + l)*256 + f];

    #pragma unroll
    for (int c = 0; c < 4; c++) {
        float v = xv[c], v2 = v*v;
        #pragma unroll
        for (int off = 16; off; off >>= 1) {
            v  += __shfl_xor_sync(0xffffffffu, v,  off);
            v2 += __shfl_xor_sync(0xffffffffu, v2, off);
        }
        if ((f & 31) == 0) { sredA[f >> 5] = v; sredB[f >> 5] = v2; }
        __syncthreads();
        if (f == 0) {
            float s = 0.f, ss = 0.f;
            #pragma unroll
            for (int w = 0; w < 8; w++) { s += sredA[w]; ss += sredB[w]; }
            sbc[0] = s * (1.f/256.f);
            sbc[1] = ss * (1.f/256.f);
        }
        __syncthreads();
        float mean = sbc[0];
        float var  = sbc[1] - mean*mean;
        float rs   = rsqrtf(var + 1e-5f);
        snx[c][f] = (xv[c] - mean) * rs * g1[c] + b1[c];
    }
    __syncthreads();

    // 3-tap conv along f for all 3 mats, 4 out channels
    float le[4], ce[4], ri[4];
    #pragma unroll
    for (int i = 0; i < 4; i++) {
        le[i] = (f > 0)   ? snx[i][f-1] : 0.f;
        ce[i] = snx[i][f];
        ri[i] = (f < 255) ? snx[i][f+1] : 0.f;
    }
    #pragma unroll
    for (int mat = 0; mat < 3; mat++) {
        #pragma unroll
        for (int o = 0; o < 4; o++) {
            float acc = 0.f;
            #pragma unroll
            for (int i = 0; i < 4; i++)
                acc += le[i]*sw[mat][o][i][0] + ce[i]*sw[mat][o][i][1] + ri[i]*sw[mat][o][i][2];
            g_conv[((size_t)(mat*4 + o)*NN + n)*256 + f] = acc;
        }
    }
}

// =================================================================================
// Kernel 2/4: per-channel SGEMM  Y[n][g] = sum_f X[n][f] * W[g][f]
//   phase 0: X = g_conv[mat][c], W = w{q,k,v}_pw[c], epilogue -> heads (+rotary, +1/16 on q)
//   phase 1: X = g_a[c],         W = wo_pw[c],       epilogue -> g_o[c][n][f]
// Tiles 64x64, K-chunks of 32, 256 threads, 4x4 register microkernel.
// =================================================================================
#define STORE_T(s, col4, row, v) { \
    s[((col4)+0)*SAS + (row)] = v.x; \
    s[((col4)+1)*SAS + (row)] = v.y; \
    s[((col4)+2)*SAS + (row)] = v.z; \
    s[((col4)+3)*SAS + (row)] = v.w; }

__global__ void __launch_bounds__(256) k_gemm(
    const float* __restrict__ wq, const float* __restrict__ wk,
    const float* __restrict__ wv, const float* __restrict__ wo, int phase)
{
    __shared__ float sA[32*SAS];
    __shared__ float sB[32*SAS];

    int t  = threadIdx.x;
    int tx = t & 15, ty = t >> 4;
    int n0 = blockIdx.x * 64;
    int g0 = blockIdx.y * 64;
    int z  = blockIdx.z;

    const float *A, *W;
    int mat, c;
    if (phase == 0) {
        mat = z >> 2; c = z & 3;
        A = g_conv + (size_t)z * NN * 256;
        W = ((mat == 0) ? wq : (mat == 1) ? wk : wv) + (size_t)c * 65536;
    } else {
        mat = 3; c = z;
        A = g_a + (size_t)c * NN * 256;
        W = wo + (size_t)c * 65536;
    }

    int lrow  = t >> 3;        // 0..31
    int lcol4 = (t & 7) * 4;   // 0..28

    float acc[4][4] = {};
    for (int k0 = 0; k0 < 256; k0 += 32) {
        #pragma unroll
        for (int r = 0; r < 2; r++) {
            int row = lrow + r*32;
            float4 av = *(const float4*)&A[(size_t)(n0 + row)*256 + k0 + lcol4];
            STORE_T(sA, lcol4, row, av);
            float4 bv = *(const float4*)&W[(size_t)(g0 + row)*256 + k0 + lcol4];
            STORE_T(sB, lcol4, row, bv);
        }
        __syncthreads();
        #pragma unroll
        for (int k = 0; k < 32; k++) {
            float4 a4 = *(const float4*)&sA[k*SAS + ty*4];
            float4 b4 = *(const float4*)&sB[k*SAS + tx*4];
            float ar[4] = {a4.x, a4.y, a4.z, a4.w};
            float br[4] = {b4.x, b4.y, b4.z, b4.w};
            #pragma unroll
            for (int i = 0; i < 4; i++)
                #pragma unroll
                for (int j = 0; j < 4; j++)
                    acc[i][j] += ar[i] * br[j];
        }
        __syncthreads();
    }

    if (phase == 1) {
        float* outp = g_o + (size_t)c * NN * 256;
        #pragma unroll
        for (int i = 0; i < 4; i++) {
            int n = n0 + ty*4 + i;
            *(float4*)&outp[(size_t)n*256 + g0 + tx*4] =
                make_float4(acc[i][0], acc[i][1], acc[i][2], acc[i][3]);
        }
    } else {
        float* outp = (mat == 0) ? g_qh : (mat == 1) ? g_kh : g_vh;
        int g = g0 + tx*4;
        int h = g >> 5, d = g & 31;
        #pragma unroll
        for (int i = 0; i < 4; i++) {
            int n = n0 + ty*4 + i;
            int b = n >> 10, l = n & 1023;
            float v0 = acc[i][0], v1 = acc[i][1], v2 = acc[i][2], v3 = acc[i][3];
            if (mat < 2) {
                int i0 = d >> 1;
                float inv0 = powf(10000.f, -(float)i0 / 16.f);
                float inv1 = powf(10000.f, -(float)(i0 + 1) / 16.f);
                float ang0 = (float)l * inv0;
                float ang1 = (float)l * inv1;
                float c0, s0, c1, s1;
                sincosf(ang0, &s0, &c0);
                sincosf(ang1, &s1, &c1);
                float r0 = v0*c0 - v1*s0;
                float r1 = v1*c0 + v0*s0;
                float r2 = v2*c1 - v3*s1;
                float r3 = v3*c1 + v2*s1;
                v0 = r0; v1 = r1; v2 = r2; v3 = r3;
                if (mat == 0) { v0 *= 0.0625f; v1 *= 0.0625f; v2 *= 0.0625f; v3 *= 0.0625f; }
            }
            size_t oi = (((size_t)(b*4 + c)*8 + h)*1024 + l)*32 + d;
            *(float4*)&outp[oi] = make_float4(v0, v1, v2, v3);
        }
    }
}

// =================================================================================
// Kernel 3: flash attention.  Per (bh, 64-row l tile):
//   qk = Q·K^T (Q pre-scaled by 1/16) + prev_qk  -> written to d_out
//   online softmax -> O = softmax(qk) @ V -> g_a[c][n][h*32+d]
// =================================================================================
__global__ void __launch_bounds__(256) k_attn(
    const float* __restrict__ prev_qk, float* __restrict__ qk_out)
{
    __shared__ float sQ[32*SAS];
    __shared__ float sK[32*SAS];
    __shared__ float sV[64*32];
    __shared__ float sP[64*64];

    int t  = threadIdx.x;
    int tx = t & 15, ty = t >> 4;
    int bh = blockIdx.y;
    int l0 = blockIdx.x * 64;

    const float* Qp  = g_qh + (size_t)bh * NL * ND;
    const float* Kp  = g_kh + (size_t)bh * NL * ND;
    const float* Vp  = g_vh + (size_t)bh * NL * ND;
    const float* Pp  = prev_qk + (size_t)bh * NL * NL;
    float*       QKo = qk_out  + (size_t)bh * NL * NL;

    int lrow  = t >> 3;
    int lcol4 = (t & 7) * 4;

    // load Q tile (64 x 32) transposed
    #pragma unroll
    for (int r = 0; r < 2; r++) {
        int row = lrow + r*32;
        float4 qv = *(const float4*)&Qp[(size_t)(l0 + row)*32 + lcol4];
        STORE_T(sQ, lcol4, row, qv);
    }

    float O[4][2] = {};
    float Mx[4], Sx[4];
    #pragma unroll
    for (int i = 0; i < 4; i++) { Mx[i] = -1e30f; Sx[i] = 0.f; }

    for (int m0 = 0; m0 < NL; m0 += 64) {
        #pragma unroll
        for (int r = 0; r < 2; r++) {
            int row = lrow + r*32;
            float4 kv = *(const float4*)&Kp[(size_t)(m0 + row)*32 + lcol4];
            STORE_T(sK, lcol4, row, kv);
        }
        ((float4*)sV)[t]       = ((const float4*)(Vp + (size_t)m0*32))[t];
        ((float4*)sV)[t + 256] = ((const float4*)(Vp + (size_t)m0*32))[t + 256];
        __syncthreads();

        // QK^T microkernel (K dim = 32)
        float acc[4][4] = {};
        #pragma unroll
        for (int d = 0; d < 32; d++) {
            float4 a4 = *(const float4*)&sQ[d*SAS + ty*4];
            float4 b4 = *(const float4*)&sK[d*SAS + tx*4];
            float ar[4] = {a4.x, a4.y, a4.z, a4.w};
            float br[4] = {b4.x, b4.y, b4.z, b4.w};
            #pragma unroll
            for (int i = 0; i < 4; i++)
                #pragma unroll
                for (int j = 0; j < 4; j++)
                    acc[i][j] += ar[i] * br[j];
        }

        // + prev_qk, write qk out, online softmax update
        #pragma unroll
        for (int i = 0; i < 4; i++) {
            int l = l0 + ty*4 + i;
            size_t off = (size_t)l*NL + m0 + tx*4;
            float4 pv = *(const float4*)&Pp[off];
            acc[i][0] += pv.x; acc[i][1] += pv.y; acc[i][2] += pv.z; acc[i][3] += pv.w;
            *(float4*)&QKo[off] = make_float4(acc[i][0], acc[i][1], acc[i][2], acc[i][3]);

            float lm = fmaxf(fmaxf(acc[i][0], acc[i][1]), fmaxf(acc[i][2], acc[i][3]));
            #pragma unroll
            for (int off2 = 8; off2; off2 >>= 1)
                lm = fmaxf(lm, __shfl_xor_sync(0xffffffffu, lm, off2));
            float nm = fmaxf(Mx[i], lm);
            float p0 = __expf(acc[i][0] - nm);
            float p1 = __expf(acc[i][1] - nm);
            float p2 = __expf(acc[i][2] - nm);
            float p3 = __expf(acc[i][3] - nm);
            float ls = p0 + p1 + p2 + p3;
            #pragma unroll
            for (int off2 = 8; off2; off2 >>= 1)
                ls += __shfl_xor_sync(0xffffffffu, ls, off2);
            float sc = __expf(Mx[i] - nm);
            Sx[i] = Sx[i]*sc + ls;
            Mx[i] = nm;
            O[i][0] *= sc; O[i][1] *= sc;
            *(float4*)&sP[(ty*4 + i)*64 + tx*4] = make_float4(p0, p1, p2, p3);
        }
        __syncthreads();

        // O += P @ V   (64 m, 2 output cols per thread)
        #pragma unroll 4
        for (int mb = 0; mb < 64; mb += 4) {
            float pr[4][4];
            #pragma unroll
            for (int i = 0; i < 4; i++) {
                float4 pv = *(const float4*)&sP[(ty*4 + i)*64 + mb];
                pr[i][0] = pv.x; pr[i][1] = pv.y; pr[i][2] = pv.z; pr[i][3] = pv.w;
            }
            #pragma unroll
            for (int mm = 0; mm < 4; mm++) {
                float2 v2 = *(const float2*)&sV[(mb + mm)*32 + tx*2];
                #pragma unroll
                for (int i = 0; i < 4; i++) {
                    O[i][0] += pr[i][mm] * v2.x;
                    O[i][1] += pr[i][mm] * v2.y;
                }
            }
        }
        __syncthreads();
    }

    int b = bh >> 5;
    int c = (bh >> 3) & 3;
    int h = bh & 7;
    #pragma unroll
    for (int i = 0; i < 4; i++) {
        int l = l0 + ty*4 + i;
        int n = b*1024 + l;
        float inv = 1.f / Sx[i];
        *(float2*)&g_a[((size_t)c*NN + n)*256 + h*32 + tx*2] =
            make_float2(O[i][0]*inv, O[i][1]*inv);
    }
}

// =================================================================================
// Kernel 5: concat(xh, o) -> inorm2 -> w1 (leaky) -> w2 -> depthwise mix -> +x
// One block per n, 256 threads.
// =================================================================================
__global__ void __launch_bounds__(256) k_ffn(
    const float* __restrict__ x,
    const float* __restrict__ g2, const float* __restrict__ b2,
    const float* __restrict__ w1, const float* __restrict__ w2,
    const float* __restrict__ dw, float* __restrict__ hout)
{
    __shared__ float sz[8][256];
    __shared__ float sz1[8][4];
    __shared__ float sredA[8], sredB[8];
    __shared__ float sbc[2];

    int f = threadIdx.x;
    int n = blockIdx.x;
    int b = n >> 10, l = n & 1023;

    float zv[8];
    #pragma unroll
    for (int c = 0; c < 4; c++) {
        zv[c]     = x[((size_t)(b*4 + c)*1024 + l)*256 + f];
        zv[4 + c] = g_o[((size_t)c*NN + n)*256 + f];
    }

    #pragma unroll
    for (int ch = 0; ch < 8; ch++) {
        float v = zv[ch], v2 = v*v;
        #pragma unroll
        for (int off = 16; off; off >>= 1) {
            v  += __shfl_xor_sync(0xffffffffu, v,  off);
            v2 += __shfl_xor_sync(0xffffffffu, v2, off);
        }
        if ((f & 31) == 0) { sredA[f >> 5] = v; sredB[f >> 5] = v2; }
        __syncthreads();
        if (f == 0) {
            float s = 0.f, ss = 0.f;
            #pragma unroll
            for (int w = 0; w < 8; w++) { s += sredA[w]; ss += sredB[w]; }
            sbc[0] = s * (1.f/256.f);
            sbc[1] = ss * (1.f/256.f);
        }
        __syncthreads();
        float mean = sbc[0];
        float var  = sbc[1] - mean*mean;
        sz[ch][f] = (zv[ch] - mean) * rsqrtf(var + 1e-5f) * g2[ch] + b2[ch];
    }
    __syncthreads();

    // z1[c][e] = sum_f sz[c][f] * w1[c][e][f]; one warp per channel c
    int w = f >> 5, lane = f & 31;
    float a0 = 0.f, a1 = 0.f, a2 = 0.f, a3 = 0.f;
    #pragma unroll
    for (int k = 0; k < 8; k++) {
        int ff = lane + 32*k;
        float zf = sz[w][ff];
        a0 += zf * w1[(w*4 + 0)*256 + ff];
        a1 += zf * w1[(w*4 + 1)*256 + ff];
        a2 += zf * w1[(w*4 + 2)*256 + ff];
        a3 += zf * w1[(w*4 + 3)*256 + ff];
    }
    #pragma unroll
    for (int off = 16; off; off >>= 1) {
        a0 += __shfl_xor_sync(0xffffffffu, a0, off);
        a1 += __shfl_xor_sync(0xffffffffu, a1, off);
        a2 += __shfl_xor_sync(0xffffffffu, a2, off);
        a3 += __shfl_xor_sync(0xffffffffu, a3, off);
    }
    if (lane == 0) {
        sz1[w][0] = (a0 > 0.f) ? a0 : 0.01f*a0;
        sz1[w][1] = (a1 > 0.f) ? a1 : 0.01f*a1;
        sz1[w][2] = (a2 > 0.f) ? a2 : 0.01f*a2;
        sz1[w][3] = (a3 > 0.f) ? a3 : 0.01f*a3;
    }
    __syncthreads();

    float ho[4] = {0.f, 0.f, 0.f, 0.f};
    #pragma unroll
    for (int c = 0; c < 8; c++) {
        float4 wv = *(const float4*)&w2[((size_t)c*256 + f)*4];
        float z2 = sz1[c][0]*wv.x + sz1[c][1]*wv.y + sz1[c][2]*wv.z + sz1[c][3]*wv.w;
        #pragma unroll
        for (int d = 0; d < 4; d++)
            ho[d] += z2 * dw[d*8 + c];
    }
    #pragma unroll
    for (int d = 0; d < 4; d++) {
        size_t idx = ((size_t)(b*4 + d)*1024 + l)*256 + f;
        hout[idx] = x[idx] + ho[d];
    }
}

// =================================================================================
extern "C" void kernel_launch(void* const* d_in, const int* in_sizes, int n_in,
                              void* d_out, int out_size)
{
    const float* x       = (const float*)d_in[0];
    const float* prev_qk = (const float*)d_in[1];
    const float* g1      = (const float*)d_in[2];
    const float* b1      = (const float*)d_in[3];
    const float* wq_conv = (const float*)d_in[4];
    const float* wk_conv = (const float*)d_in[5];
    const float* wv_conv = (const float*)d_in[6];
    const float* wq_pw   = (const float*)d_in[7];
    const float* wk_pw   = (const float*)d_in[8];
    const float* wv_pw   = (const float*)d_in[9];
    const float* wo_pw   = (const float*)d_in[10];
    const float* g2      = (const float*)d_in[11];
    const float* b2      = (const float*)d_in[12];
    const float* w1_pw   = (const float*)d_in[13];
    const float* w2_pw   = (const float*)d_in[14];
    const float* w2_dw   = (const float*)d_in[15];

    float* out  = (float*)d_out;
    float* qk_o = out + HOUT_SIZE;

    k_norm_conv<<<NN, 256>>>(x, g1, b1, wq_conv, wk_conv, wv_conv);
    k_gemm<<<dim3(32, 4, 12), 256>>>(wq_pw, wk_pw, wv_pw, wo_pw, 0);
    k_attn<<<dim3(16, NBH), 256>>>(prev_qk, qk_o);
    k_gemm<<<dim3(32, 4, 4), 256>>>(wq_pw, wk_pw, wv_pw, wo_pw, 1);
    k_ffn<<<NN, 256>>>(x, g2, b2, w1_pw, w2_pw, w2_dw, out);
}

// round 2
// speedup vs baseline: 1.0608x; 1.0608x over previous
#include <cuda_runtime.h>
#include <math.h>

// Problem constants
#define NB 2
#define NC 4
#define NL 1024
#define NF 256
#define NH 8
#define ND 32
#define NN (NB*NL)          // 2048 samples
#define NBH (NB*NC*NH)      // 64 attention slices
#define HOUT_SIZE (NB*NC*NL*NF)  // 2097152

#define SAS  68   // padded stride for 64-wide transposed tiles
#define SAS2 132  // padded stride for 128-wide transposed tiles

// ------------------- scratch (static device memory; no allocs) -------------------
__device__ float g_conv[3 * NC * NN * NF];  // conv outputs for q,k,v
__device__ float g_qh[NBH * NL * ND];       // rotated+scaled Q heads
__device__ float g_kh[NBH * NL * ND];       // rotated K heads
__device__ float g_vh[NBH * NL * ND];       // V heads
__device__ float g_a [NC * NN * NF];        // attention output, [c][n][f]
__device__ float g_o [NC * NN * NF];        // wo output, [c][n][f]

#define STORE_T(s, stride, col4, row, v) { \
    s[((col4)+0)*(stride) + (row)] = v.x; \
    s[((col4)+1)*(stride) + (row)] = v.y; \
    s[((col4)+2)*(stride) + (row)] = v.z; \
    s[((col4)+3)*(stride) + (row)] = v.w; }

// =================================================================================
// Kernel 1: instance-norm (per n, per channel over 256) + 3-tap conv -> g_conv
// =================================================================================
__global__ void __launch_bounds__(256) k_norm_conv(
    const float* __restrict__ x,
    const float* __restrict__ g1, const float* __restrict__ b1,
    const float* __restrict__ wq, const float* __restrict__ wk, const float* __restrict__ wv)
{
    __shared__ float snx[4][256];
    __shared__ float sw[3][4][4][3];   // [mat][o][i][kh]
    __shared__ float sredA[8], sredB[8];
    __shared__ float sbc[2];

    int f = threadIdx.x;
    int n = blockIdx.x;
    int b = n >> 10, l = n & 1023;

    if (f < 144) {
        int mat = f / 48, rem = f % 48;
        int o = rem / 12, i = (rem % 12) / 3, kh = rem % 3;
        const float* wsrc = (mat == 0) ? wq : (mat == 1) ? wk : wv;
        sw[mat][o][i][kh] = wsrc[(o*4 + i)*9 + kh*3 + 1];  // kw=1 slice only (W=1)
    }

    float xv[4];
    #pragma unroll
    for (int c = 0; c < 4; c++)
        xv[c] = x[((size_t)(b*4 + c)*1024 + l)*256 + f];

    #pragma unroll
    for (int c = 0; c < 4; c++) {
        float v = xv[c], v2 = v*v;
        #pragma unroll
        for (int off = 16; off; off >>= 1) {
            v  += __shfl_xor_sync(0xffffffffu, v,  off);
            v2 += __shfl_xor_sync(0xffffffffu, v2, off);
        }
        if ((f & 31) == 0) { sredA[f >> 5] = v; sredB[f >> 5] = v2; }
        __syncthreads();
        if (f == 0) {
            float s = 0.f, ss = 0.f;
            #pragma unroll
            for (int w = 0; w < 8; w++) { s += sredA[w]; ss += sredB[w]; }
            sbc[0] = s * (1.f/256.f);
            sbc[1] = ss * (1.f/256.f);
        }
        __syncthreads();
        float mean = sbc[0];
        float var  = sbc[1] - mean*mean;
        float rs   = rsqrtf(var + 1e-5f);
        snx[c][f] = (xv[c] - mean) * rs * g1[c] + b1[c];
    }
    __syncthreads();

    float le[4], ce[4], ri[4];
    #pragma unroll
    for (int i = 0; i < 4; i++) {
        le[i] = (f > 0)   ? snx[i][f-1] : 0.f;
        ce[i] = snx[i][f];
        ri[i] = (f < 255) ? snx[i][f+1] : 0.f;
    }
    #pragma unroll
    for (int mat = 0; mat < 3; mat++) {
        #pragma unroll
        for (int o = 0; o < 4; o++) {
            float acc = 0.f;
            #pragma unroll
            for (int i = 0; i < 4; i++)
                acc += le[i]*sw[mat][o][i][0] + ce[i]*sw[mat][o][i][1] + ri[i]*sw[mat][o][i][2];
            g_conv[((size_t)(mat*4 + o)*NN + n)*256 + f] = acc;
        }
    }
}

// =================================================================================
// Kernel 2/4: per-channel SGEMM  Y[n][g] = sum_f X[n][f] * W[g][f]
// 128x128 tile, 256 threads, 8x8 register microkernel, K-chunks of 32.
//   phase 0: X = g_conv[mat][c], W = w{q,k,v}_pw[c], epilogue -> heads (+rotary)
//   phase 1: X = g_a[c],         W = wo_pw[c],       epilogue -> g_o[c][n][f]
// =================================================================================
__global__ void __launch_bounds__(256) k_gemm(
    const float* __restrict__ wq, const float* __restrict__ wk,
    const float* __restrict__ wv, const float* __restrict__ wo, int phase)
{
    __shared__ float sA[32*SAS2];
    __shared__ float sB[32*SAS2];

    int t  = threadIdx.x;
    int tx = t & 15, ty = t >> 4;
    int n0 = blockIdx.x * 128;
    int g0 = blockIdx.y * 128;
    int z  = blockIdx.z;

    const float *A, *W;
    int mat, c;
    if (phase == 0) {
        mat = z >> 2; c = z & 3;
        A = g_conv + (size_t)z * NN * 256;
        W = ((mat == 0) ? wq : (mat == 1) ? wk : wv) + (size_t)c * 65536;
    } else {
        mat = 3; c = z;
        A = g_a + (size_t)c * NN * 256;
        W = wo + (size_t)c * 65536;
    }

    int lrow  = t >> 3;        // 0..31
    int lcol4 = (t & 7) * 4;   // 0..28

    float acc[8][8] = {};
    for (int k0 = 0; k0 < 256; k0 += 32) {
        #pragma unroll
        for (int r = 0; r < 4; r++) {
            int row = lrow + r*32;
            float4 av = *(const float4*)&A[(size_t)(n0 + row)*256 + k0 + lcol4];
            STORE_T(sA, SAS2, lcol4, row, av);
            float4 bv = *(const float4*)&W[(size_t)(g0 + row)*256 + k0 + lcol4];
            STORE_T(sB, SAS2, lcol4, row, bv);
        }
        __syncthreads();
        #pragma unroll
        for (int k = 0; k < 32; k++) {
            float4 a0 = *(const float4*)&sA[k*SAS2 + ty*4];
            float4 a1 = *(const float4*)&sA[k*SAS2 + 64 + ty*4];
            float4 b0 = *(const float4*)&sB[k*SAS2 + tx*4];
            float4 b1 = *(const float4*)&sB[k*SAS2 + 64 + tx*4];
            float ar[8] = {a0.x,a0.y,a0.z,a0.w, a1.x,a1.y,a1.z,a1.w};
            float br[8] = {b0.x,b0.y,b0.z,b0.w, b1.x,b1.y,b1.z,b1.w};
            #pragma unroll
            for (int i = 0; i < 8; i++)
                #pragma unroll
                for (int j = 0; j < 8; j++)
                    acc[i][j] += ar[i] * br[j];
        }
        __syncthreads();
    }

    if (phase == 1) {
        float* outp = g_o + (size_t)c * NN * 256;
        #pragma unroll
        for (int ii = 0; ii < 2; ii++)
        #pragma unroll
        for (int i = 0; i < 4; i++) {
            int n = n0 + ii*64 + ty*4 + i;
            #pragma unroll
            for (int jj = 0; jj < 2; jj++) {
                *(float4*)&outp[(size_t)n*256 + g0 + jj*64 + tx*4] =
                    make_float4(acc[ii*4+i][jj*4+0], acc[ii*4+i][jj*4+1],
                                acc[ii*4+i][jj*4+2], acc[ii*4+i][jj*4+3]);
            }
        }
    } else {
        float* outp = (mat == 0) ? g_qh : (mat == 1) ? g_kh : g_vh;
        int d = (tx*4) & 31;           // same d for both jj column groups
        int i0 = d >> 1;
        float inv0 = 0.f, inv1 = 0.f;
        if (mat < 2) {
            inv0 = powf(10000.f, -(float)i0 / 16.f);
            inv1 = powf(10000.f, -(float)(i0 + 1) / 16.f);
        }
        #pragma unroll
        for (int ii = 0; ii < 2; ii++)
        #pragma unroll
        for (int i = 0; i < 4; i++) {
            int n = n0 + ii*64 + ty*4 + i;
            int b = n >> 10, l = n & 1023;
            float c0=1.f, s0=0.f, c1=1.f, s1=0.f;
            if (mat < 2) {
                sincosf((float)l * inv0, &s0, &c0);
                sincosf((float)l * inv1, &s1, &c1);
            }
            #pragma unroll
            for (int jj = 0; jj < 2; jj++) {
                int g = g0 + jj*64 + tx*4;
                int h = g >> 5;
                float v0 = acc[ii*4+i][jj*4+0], v1 = acc[ii*4+i][jj*4+1];
                float v2 = acc[ii*4+i][jj*4+2], v3 = acc[ii*4+i][jj*4+3];
                if (mat < 2) {
                    float r0 = v0*c0 - v1*s0;
                    float r1 = v1*c0 + v0*s0;
                    float r2 = v2*c1 - v3*s1;
                    float r3 = v3*c1 + v2*s1;
                    v0 = r0; v1 = r1; v2 = r2; v3 = r3;
                    if (mat == 0) { v0 *= 0.0625f; v1 *= 0.0625f; v2 *= 0.0625f; v3 *= 0.0625f; }
                }
                size_t oi = (((size_t)(b*4 + c)*8 + h)*1024 + l)*32 + d;
                *(float4*)&outp[oi] = make_float4(v0, v1, v2, v3);
            }
        }
    }
}

// =================================================================================
// Kernel 3: flash attention. 128-row l tiles x 64-col m tiles.
//   qk = Q·K^T (Q pre-scaled by 1/16) + prev_qk -> written to d_out
//   online softmax -> O = softmax(qk) @ V -> g_a[c][n][h*32+d]
// =================================================================================
__global__ void __launch_bounds__(256) k_attn(
    const float* __restrict__ prev_qk, float* __restrict__ qk_out)
{
    __shared__ float sQ[32*SAS2];   // [d][row 0..127]
    __shared__ float sK[32*SAS];    // [d][row 0..63]
    __shared__ float sV[64*32];
    __shared__ float sP[128*64];

    int t  = threadIdx.x;
    int tx = t & 15, ty = t >> 4;
    int bh = blockIdx.y;
    int l0 = blockIdx.x * 128;

    const float* Qp  = g_qh + (size_t)bh * NL * ND;
    const float* Kp  = g_kh + (size_t)bh * NL * ND;
    const float* Vp  = g_vh + (size_t)bh * NL * ND;
    const float* Pp  = prev_qk + (size_t)bh * NL * NL;
    float*       QKo = qk_out  + (size_t)bh * NL * NL;

    int lrow  = t >> 3;
    int lcol4 = (t & 7) * 4;

    // load Q tile (128 x 32) transposed
    #pragma unroll
    for (int r = 0; r < 4; r++) {
        int row = lrow + r*32;
        float4 qv = *(const float4*)&Qp[(size_t)(l0 + row)*32 + lcol4];
        STORE_T(sQ, SAS2, lcol4, row, qv);
    }

    float O[8][2] = {};
    float Mx[8], Sx[8];
    #pragma unroll
    for (int i = 0; i < 8; i++) { Mx[i] = -1e30f; Sx[i] = 0.f; }

    for (int m0 = 0; m0 < NL; m0 += 64) {
        #pragma unroll
        for (int r = 0; r < 2; r++) {
            int row = lrow + r*32;
            float4 kv = *(const float4*)&Kp[(size_t)(m0 + row)*32 + lcol4];
            STORE_T(sK, SAS, lcol4, row, kv);
        }
        ((float4*)sV)[t]       = ((const float4*)(Vp + (size_t)m0*32))[t];
        ((float4*)sV)[t + 256] = ((const float4*)(Vp + (size_t)m0*32))[t + 256];
        __syncthreads();

        // QK^T microkernel: 8 rows x 4 cols per thread
        float acc[8][4] = {};
        #pragma unroll
        for (int d = 0; d < 32; d++) {
            float4 a0 = *(const float4*)&sQ[d*SAS2 + ty*4];
            float4 a1 = *(const float4*)&sQ[d*SAS2 + 64 + ty*4];
            float4 bv = *(const float4*)&sK[d*SAS + tx*4];
            float ar[8] = {a0.x,a0.y,a0.z,a0.w, a1.x,a1.y,a1.z,a1.w};
            float br[4] = {bv.x,bv.y,bv.z,bv.w};
            #pragma unroll
            for (int i = 0; i < 8; i++)
                #pragma unroll
                for (int j = 0; j < 4; j++)
                    acc[i][j] += ar[i] * br[j];
        }

        // + prev_qk, write qk out, online softmax update
        #pragma unroll
        for (int ri = 0; ri < 8; ri++) {
            int row = (ri >> 2)*64 + ty*4 + (ri & 3);
            int l = l0 + row;
            size_t off = (size_t)l*NL + m0 + tx*4;
            float4 pv = *(const float4*)&Pp[off];
            acc[ri][0] += pv.x; acc[ri][1] += pv.y; acc[ri][2] += pv.z; acc[ri][3] += pv.w;
            *(float4*)&QKo[off] = make_float4(acc[ri][0], acc[ri][1], acc[ri][2], acc[ri][3]);

            float lm = fmaxf(fmaxf(acc[ri][0], acc[ri][1]), fmaxf(acc[ri][2], acc[ri][3]));
            #pragma unroll
            for (int off2 = 8; off2; off2 >>= 1)
                lm = fmaxf(lm, __shfl_xor_sync(0xffffffffu, lm, off2));
            float nm = fmaxf(Mx[ri], lm);
            float p0 = __expf(acc[ri][0] - nm);
            float p1 = __expf(acc[ri][1] - nm);
            float p2 = __expf(acc[ri][2] - nm);
            float p3 = __expf(acc[ri][3] - nm);
            float ls = p0 + p1 + p2 + p3;
            #pragma unroll
            for (int off2 = 8; off2; off2 >>= 1)
                ls += __shfl_xor_sync(0xffffffffu, ls, off2);
            float sc = __expf(Mx[ri] - nm);
            Sx[ri] = Sx[ri]*sc + ls;
            Mx[ri] = nm;
            O[ri][0] *= sc; O[ri][1] *= sc;
            *(float4*)&sP[row*64 + tx*4] = make_float4(p0, p1, p2, p3);
        }
        __syncthreads();

        // O += P @ V
        #pragma unroll 4
        for (int mb = 0; mb < 64; mb += 4) {
            float pr[8][4];
            #pragma unroll
            for (int ri = 0; ri < 8; ri++) {
                int row = (ri >> 2)*64 + ty*4 + (ri & 3);
                float4 pv = *(const float4*)&sP[row*64 + mb];
                pr[ri][0] = pv.x; pr[ri][1] = pv.y; pr[ri][2] = pv.z; pr[ri][3] = pv.w;
            }
            #pragma unroll
            for (int mm = 0; mm < 4; mm++) {
                float2 v2 = *(const float2*)&sV[(mb + mm)*32 + tx*2];
                #pragma unroll
                for (int ri = 0; ri < 8; ri++) {
                    O[ri][0] += pr[ri][mm] * v2.x;
                    O[ri][1] += pr[ri][mm] * v2.y;
                }
            }
        }
        __syncthreads();
    }

    int b = bh >> 5;
    int c = (bh >> 3) & 3;
    int h = bh & 7;
    #pragma unroll
    for (int ri = 0; ri < 8; ri++) {
        int row = (ri >> 2)*64 + ty*4 + (ri & 3);
        int l = l0 + row;
        int n = b*1024 + l;
        float inv = 1.f / Sx[ri];
        *(float2*)&g_a[((size_t)c*NN + n)*256 + h*32 + tx*2] =
            make_float2(O[ri][0]*inv, O[ri][1]*inv);
    }
}

// =================================================================================
// Kernel 5: concat(xh, o) -> inorm2 -> w1 (leaky) -> w2 -> depthwise mix -> +x
// =================================================================================
__global__ void __launch_bounds__(256) k_ffn(
    const float* __restrict__ x,
    const float* __restrict__ g2, const float* __restrict__ b2,
    const float* __restrict__ w1, const float* __restrict__ w2,
    const float* __restrict__ dw, float* __restrict__ hout)
{
    __shared__ float sz[8][256];
    __shared__ float sz1[8][4];
    __shared__ float sredA[8], sredB[8];
    __shared__ float sbc[2];

    int f = threadIdx.x;
    int n = blockIdx.x;
    int b = n >> 10, l = n & 1023;

    float zv[8];
    #pragma unroll
    for (int c = 0; c < 4; c++) {
        zv[c]     = x[((size_t)(b*4 + c)*1024 + l)*256 + f];
        zv[4 + c] = g_o[((size_t)c*NN + n)*256 + f];
    }

    #pragma unroll
    for (int ch = 0; ch < 8; ch++) {
        float v = zv[ch], v2 = v*v;
        #pragma unroll
        for (int off = 16; off; off >>= 1) {
            v  += __shfl_xor_sync(0xffffffffu, v,  off);
            v2 += __shfl_xor_sync(0xffffffffu, v2, off);
        }
        if ((f & 31) == 0) { sredA[f >> 5] = v; sredB[f >> 5] = v2; }
        __syncthreads();
        if (f == 0) {
            float s = 0.f, ss = 0.f;
            #pragma unroll
            for (int w = 0; w < 8; w++) { s += sredA[w]; ss += sredB[w]; }
            sbc[0] = s * (1.f/256.f);
            sbc[1] = ss * (1.f/256.f);
        }
        __syncthreads();
        float mean = sbc[0];
        float var  = sbc[1] - mean*mean;
        sz[ch][f] = (zv[ch] - mean) * rsqrtf(var + 1e-5f) * g2[ch] + b2[ch];
    }
    __syncthreads();

    int w = f >> 5, lane = f & 31;
    float a0 = 0.f, a1 = 0.f, a2 = 0.f, a3 = 0.f;
    #pragma unroll
    for (int k = 0; k < 8; k++) {
        int ff = lane + 32*k;
        float zf = sz[w][ff];
        a0 += zf * w1[(w*4 + 0)*256 + ff];
        a1 += zf * w1[(w*4 + 1)*256 + ff];
        a2 += zf * w1[(w*4 + 2)*256 + ff];
        a3 += zf * w1[(w*4 + 3)*256 + ff];
    }
    #pragma unroll
    for (int off = 16; off; off >>= 1) {
        a0 += __shfl_xor_sync(0xffffffffu, a0, off);
        a1 += __shfl_xor_sync(0xffffffffu, a1, off);
        a2 += __shfl_xor_sync(0xffffffffu, a2, off);
        a3 += __shfl_xor_sync(0xffffffffu, a3, off);
    }
    if (lane == 0) {
        sz1[w][0] = (a0 > 0.f) ? a0 : 0.01f*a0;
        sz1[w][1] = (a1 > 0.f) ? a1 : 0.01f*a1;
        sz1[w][2] = (a2 > 0.f) ? a2 : 0.01f*a2;
        sz1[w][3] = (a3 > 0.f) ? a3 : 0.01f*a3;
    }
    __syncthreads();

    float ho[4] = {0.f, 0.f, 0.f, 0.f};
    #pragma unroll
    for (int c = 0; c < 8; c++) {
        float4 wv = *(const float4*)&w2[((size_t)c*256 + f)*4];
        float z2 = sz1[c][0]*wv.x + sz1[c][1]*wv.y + sz1[c][2]*wv.z + sz1[c][3]*wv.w;
        #pragma unroll
        for (int d = 0; d < 4; d++)
            ho[d] += z2 * dw[d*8 + c];
    }
    #pragma unroll
    for (int d = 0; d < 4; d++) {
        size_t idx = ((size_t)(b*4 + d)*1024 + l)*256 + f;
        hout[idx] = x[idx] + ho[d];
    }
}

// =================================================================================
extern "C" void kernel_launch(void* const* d_in, const int* in_sizes, int n_in,
                              void* d_out, int out_size)
{
    const float* x       = (const float*)d_in[0];
    const float* prev_qk = (const float*)d_in[1];
    const float* g1      = (const float*)d_in[2];
    const float* b1      = (const float*)d_in[3];
    const float* wq_conv = (const float*)d_in[4];
    const float* wk_conv = (const float*)d_in[5];
    const float* wv_conv = (const float*)d_in[6];
    const float* wq_pw   = (const float*)d_in[7];
    const float* wk_pw   = (const float*)d_in[8];
    const float* wv_pw   = (const float*)d_in[9];
    const float* wo_pw   = (const float*)d_in[10];
    const float* g2      = (const float*)d_in[11];
    const float* b2      = (const float*)d_in[12];
    const float* w1_pw   = (const float*)d_in[13];
    const float* w2_pw   = (const float*)d_in[14];
    const float* w2_dw   = (const float*)d_in[15];

    float* out  = (float*)d_out;
    float* qk_o = out + HOUT_SIZE;

    k_norm_conv<<<NN, 256>>>(x, g1, b1, wq_conv, wk_conv, wv_conv);
    k_gemm<<<dim3(16, 2, 12), 256>>>(wq_pw, wk_pw, wv_pw, wo_pw, 0);
    k_attn<<<dim3(8, NBH), 256>>>(prev_qk, qk_o);
    k_gemm<<<dim3(16, 2, 4), 256>>>(wq_pw, wk_pw, wv_pw, wo_pw, 1);
    k_ffn<<<NN, 256>>>(x, g2, b2, w1_pw, w2_pw, w2_dw, out);
}

// round 3
// speedup vs baseline: 1.1170x; 1.0530x over previous
#include <cuda_runtime.h>
#include <math.h>

// Problem constants
#define NB 2
#define NC 4
#define NL 1024
#define NF 256
#define NH 8
#define ND 32
#define NN (NB*NL)          // 2048 samples
#define NBH (NB*NC*NH)      // 64 attention slices
#define HOUT_SIZE (NB*NC*NL*NF)  // 2097152

#define SAS  68   // padded stride for 64-wide transposed tiles
#define SAS2 132  // padded stride for 128-wide transposed tiles

typedef unsigned long long ull;

// packed f32x2 helpers (fma.rn.f32x2: 2 FMAs per fma-pipe slot on sm_103a)
__device__ __forceinline__ ull pk(float lo, float hi) {
    ull r; asm("mov.b64 %0, {%1,%2};" : "=l"(r) : "f"(lo), "f"(hi)); return r;
}
__device__ __forceinline__ void upk(float& lo, float& hi, ull v) {
    asm("mov.b64 {%0,%1}, %2;" : "=f"(lo), "=f"(hi) : "l"(v));
}
__device__ __forceinline__ void fma2(ull& d, ull a, ull b) {
    asm("fma.rn.f32x2 %0, %1, %2, %3;" : "=l"(d) : "l"(a), "l"(b), "l"(d));
}
__device__ __forceinline__ void mul2(ull& d, ull a, ull b) {
    asm("mul.rn.f32x2 %0, %1, %2;" : "=l"(d) : "l"(a), "l"(b));
}

// ------------------- scratch (static device memory; no allocs) -------------------
__device__ float g_conv[3 * NC * NN * NF];  // conv outputs for q,k,v
__device__ float g_qh[NBH * NL * ND];       // rotated+scaled Q heads
__device__ float g_kh[NBH * NL * ND];       // rotated K heads
__device__ float g_vh[NBH * NL * ND];       // V heads
__device__ float g_a [NC * NN * NF];        // attention output, [c][n][f]
__device__ float g_o [NC * NN * NF];        // wo output, [c][n][f]

#define STORE_T(s, stride, col4, row, v) { \
    s[((col4)+0)*(stride) + (row)] = v.x; \
    s[((col4)+1)*(stride) + (row)] = v.y; \
    s[((col4)+2)*(stride) + (row)] = v.z; \
    s[((col4)+3)*(stride) + (row)] = v.w; }

// =================================================================================
// Kernel 1: instance-norm (per n, per channel over 256) + 3-tap conv -> g_conv
// =================================================================================
__global__ void __launch_bounds__(256) k_norm_conv(
    const float* __restrict__ x,
    const float* __restrict__ g1, const float* __restrict__ b1,
    const float* __restrict__ wq, const float* __restrict__ wk, const float* __restrict__ wv)
{
    __shared__ float snx[4][256];
    __shared__ float sw[3][4][4][3];
    __shared__ float sredA[8], sredB[8];
    __shared__ float sbc[2];

    int f = threadIdx.x;
    int n = blockIdx.x;
    int b = n >> 10, l = n & 1023;

    if (f < 144) {
        int mat = f / 48, rem = f % 48;
        int o = rem / 12, i = (rem % 12) / 3, kh = rem % 3;
        const float* wsrc = (mat == 0) ? wq : (mat == 1) ? wk : wv;
        sw[mat][o][i][kh] = wsrc[(o*4 + i)*9 + kh*3 + 1];
    }

    float xv[4];
    #pragma unroll
    for (int c = 0; c < 4; c++)
        xv[c] = x[((size_t)(b*4 + c)*1024 + l)*256 + f];

    #pragma unroll
    for (int c = 0; c < 4; c++) {
        float v = xv[c], v2 = v*v;
        #pragma unroll
        for (int off = 16; off; off >>= 1) {
            v  += __shfl_xor_sync(0xffffffffu, v,  off);
            v2 += __shfl_xor_sync(0xffffffffu, v2, off);
        }
        if ((f & 31) == 0) { sredA[f >> 5] = v; sredB[f >> 5] = v2; }
        __syncthreads();
        if (f == 0) {
            float s = 0.f, ss = 0.f;
            #pragma unroll
            for (int w = 0; w < 8; w++) { s += sredA[w]; ss += sredB[w]; }
            sbc[0] = s * (1.f/256.f);
            sbc[1] = ss * (1.f/256.f);
        }
        __syncthreads();
        float mean = sbc[0];
        float var  = sbc[1] - mean*mean;
        float rs   = rsqrtf(var + 1e-5f);
        snx[c][f] = (xv[c] - mean) * rs * g1[c] + b1[c];
    }
    __syncthreads();

    float le[4], ce[4], ri[4];
    #pragma unroll
    for (int i = 0; i < 4; i++) {
        le[i] = (f > 0)   ? snx[i][f-1] : 0.f;
        ce[i] = snx[i][f];
        ri[i] = (f < 255) ? snx[i][f+1] : 0.f;
    }
    #pragma unroll
    for (int mat = 0; mat < 3; mat++) {
        #pragma unroll
        for (int o = 0; o < 4; o++) {
            float acc = 0.f;
            #pragma unroll
            for (int i = 0; i < 4; i++)
                acc += le[i]*sw[mat][o][i][0] + ce[i]*sw[mat][o][i][1] + ri[i]*sw[mat][o][i][2];
            g_conv[((size_t)(mat*4 + o)*NN + n)*256 + f] = acc;
        }
    }
}

// =================================================================================
// Kernel 2/4: per-channel SGEMM, 128x128 tile, 8x8 micro via f32x2, reg prefetch.
// =================================================================================
__global__ void __launch_bounds__(256) k_gemm(
    const float* __restrict__ wq, const float* __restrict__ wk,
    const float* __restrict__ wv, const float* __restrict__ wo, int phase)
{
    __shared__ float sA[32*SAS2];
    __shared__ float sB[32*SAS2];

    int t  = threadIdx.x;
    int tx = t & 15, ty = t >> 4;
    int n0 = blockIdx.x * 128;
    int g0 = blockIdx.y * 128;
    int z  = blockIdx.z;

    const float *A, *W;
    int mat, c;
    if (phase == 0) {
        mat = z >> 2; c = z & 3;
        A = g_conv + (size_t)z * NN * 256;
        W = ((mat == 0) ? wq : (mat == 1) ? wk : wv) + (size_t)c * 65536;
    } else {
        mat = 3; c = z;
        A = g_a + (size_t)c * NN * 256;
        W = wo + (size_t)c * 65536;
    }

    int lrow  = t >> 3;        // 0..31
    int lcol4 = (t & 7) * 4;   // 0..28

    // prefetch chunk 0
    float4 pav[4], pbv[4];
    #pragma unroll
    for (int r = 0; r < 4; r++) {
        pav[r] = *(const float4*)&A[(size_t)(n0 + lrow + r*32)*256 + lcol4];
        pbv[r] = *(const float4*)&W[(size_t)(g0 + lrow + r*32)*256 + lcol4];
    }

    ull acc2[8][4];
    #pragma unroll
    for (int i = 0; i < 8; i++)
        #pragma unroll
        for (int j = 0; j < 4; j++) acc2[i][j] = 0ull;

    for (int k0 = 0; k0 < 256; k0 += 32) {
        #pragma unroll
        for (int r = 0; r < 4; r++) {
            int row = lrow + r*32;
            STORE_T(sA, SAS2, lcol4, row, pav[r]);
            STORE_T(sB, SAS2, lcol4, row, pbv[r]);
        }
        __syncthreads();
        if (k0 < 224) {
            #pragma unroll
            for (int r = 0; r < 4; r++) {
                pav[r] = *(const float4*)&A[(size_t)(n0 + lrow + r*32)*256 + k0 + 32 + lcol4];
                pbv[r] = *(const float4*)&W[(size_t)(g0 + lrow + r*32)*256 + k0 + 32 + lcol4];
            }
        }
        #pragma unroll
        for (int k = 0; k < 32; k++) {
            float4 a0 = *(const float4*)&sA[k*SAS2 + ty*4];
            float4 a1 = *(const float4*)&sA[k*SAS2 + 64 + ty*4];
            float4 b0 = *(const float4*)&sB[k*SAS2 + tx*4];
            float4 b1 = *(const float4*)&sB[k*SAS2 + 64 + tx*4];
            ull bp[4] = { pk(b0.x,b0.y), pk(b0.z,b0.w), pk(b1.x,b1.y), pk(b1.z,b1.w) };
            float ar[8] = {a0.x,a0.y,a0.z,a0.w, a1.x,a1.y,a1.z,a1.w};
            #pragma unroll
            for (int i = 0; i < 8; i++) {
                ull ap = pk(ar[i], ar[i]);
                fma2(acc2[i][0], ap, bp[0]);
                fma2(acc2[i][1], ap, bp[1]);
                fma2(acc2[i][2], ap, bp[2]);
                fma2(acc2[i][3], ap, bp[3]);
            }
        }
        __syncthreads();
    }

    if (phase == 1) {
        float* outp = g_o + (size_t)c * NN * 256;
        #pragma unroll
        for (int ii = 0; ii < 2; ii++)
        #pragma unroll
        for (int i = 0; i < 4; i++) {
            int n = n0 + ii*64 + ty*4 + i;
            #pragma unroll
            for (int jj = 0; jj < 2; jj++) {
                float v0,v1,v2,v3;
                upk(v0, v1, acc2[ii*4+i][jj*2+0]);
                upk(v2, v3, acc2[ii*4+i][jj*2+1]);
                *(float4*)&outp[(size_t)n*256 + g0 + jj*64 + tx*4] =
                    make_float4(v0, v1, v2, v3);
            }
        }
    } else {
        float* outp = (mat == 0) ? g_qh : (mat == 1) ? g_kh : g_vh;
        int d = (tx*4) & 31;
        int i0 = d >> 1;
        float inv0 = 0.f, inv1 = 0.f;
        if (mat < 2) {
            inv0 = powf(10000.f, -(float)i0 / 16.f);
            inv1 = powf(10000.f, -(float)(i0 + 1) / 16.f);
        }
        #pragma unroll
        for (int ii = 0; ii < 2; ii++)
        #pragma unroll
        for (int i = 0; i < 4; i++) {
            int n = n0 + ii*64 + ty*4 + i;
            int b = n >> 10, l = n & 1023;
            float c0=1.f, s0=0.f, c1=1.f, s1=0.f;
            if (mat < 2) {
                sincosf((float)l * inv0, &s0, &c0);
                sincosf((float)l * inv1, &s1, &c1);
            }
            #pragma unroll
            for (int jj = 0; jj < 2; jj++) {
                int g = g0 + jj*64 + tx*4;
                int h = g >> 5;
                float v0,v1,v2,v3;
                upk(v0, v1, acc2[ii*4+i][jj*2+0]);
                upk(v2, v3, acc2[ii*4+i][jj*2+1]);
                if (mat < 2) {
                    float r0 = v0*c0 - v1*s0;
                    float r1 = v1*c0 + v0*s0;
                    float r2 = v2*c1 - v3*s1;
                    float r3 = v3*c1 + v2*s1;
                    v0 = r0; v1 = r1; v2 = r2; v3 = r3;
                    if (mat == 0) { v0 *= 0.0625f; v1 *= 0.0625f; v2 *= 0.0625f; v3 *= 0.0625f; }
                }
                size_t oi = (((size_t)(b*4 + c)*8 + h)*1024 + l)*32 + d;
                *(float4*)&outp[oi] = make_float4(v0, v1, v2, v3);
            }
        }
    }
}

// =================================================================================
// Kernel 3: flash attention, 128-row l tiles x 64-col m tiles, f32x2 microkernels,
// prev_qk prefetched into registers ahead of the QK compute.
// =================================================================================
__global__ void __launch_bounds__(256) k_attn(
    const float* __restrict__ prev_qk, float* __restrict__ qk_out)
{
    __shared__ float sQ[32*SAS2];   // [d][row 0..127]
    __shared__ float sK[32*SAS];    // [d][row 0..63]
    __shared__ float sV[64*32];
    __shared__ float sP[128*64];

    int t  = threadIdx.x;
    int tx = t & 15, ty = t >> 4;
    int bh = blockIdx.y;
    int l0 = blockIdx.x * 128;

    const float* Qp  = g_qh + (size_t)bh * NL * ND;
    const float* Kp  = g_kh + (size_t)bh * NL * ND;
    const float* Vp  = g_vh + (size_t)bh * NL * ND;
    const float* Pp  = prev_qk + (size_t)bh * NL * NL;
    float*       QKo = qk_out  + (size_t)bh * NL * NL;

    int lrow  = t >> 3;
    int lcol4 = (t & 7) * 4;

    #pragma unroll
    for (int r = 0; r < 4; r++) {
        int row = lrow + r*32;
        float4 qv = *(const float4*)&Qp[(size_t)(l0 + row)*32 + lcol4];
        STORE_T(sQ, SAS2, lcol4, row, qv);
    }

    ull O2[8];
    float Mx[8], Sx[8];
    #pragma unroll
    for (int i = 0; i < 8; i++) { O2[i] = 0ull; Mx[i] = -1e30f; Sx[i] = 0.f; }

    for (int m0 = 0; m0 < NL; m0 += 64) {
        #pragma unroll
        for (int r = 0; r < 2; r++) {
            int row = lrow + r*32;
            float4 kv = *(const float4*)&Kp[(size_t)(m0 + row)*32 + lcol4];
            STORE_T(sK, SAS, lcol4, row, kv);
        }
        ((float4*)sV)[t]       = ((const float4*)(Vp + (size_t)m0*32))[t];
        ((float4*)sV)[t + 256] = ((const float4*)(Vp + (size_t)m0*32))[t + 256];

        // prefetch prev_qk tile (DRAM) — consumed after the QK microkernel
        float4 pv[8];
        #pragma unroll
        for (int ri = 0; ri < 8; ri++) {
            int row = (ri >> 2)*64 + ty*4 + (ri & 3);
            pv[ri] = *(const float4*)&Pp[(size_t)(l0 + row)*NL + m0 + tx*4];
        }
        __syncthreads();

        // QK^T microkernel: 8 rows x 2 col-pairs per thread (f32x2)
        ull acc2[8][2];
        #pragma unroll
        for (int i = 0; i < 8; i++) { acc2[i][0] = 0ull; acc2[i][1] = 0ull; }
        #pragma unroll
        for (int d = 0; d < 32; d++) {
            float4 a0 = *(const float4*)&sQ[d*SAS2 + ty*4];
            float4 a1 = *(const float4*)&sQ[d*SAS2 + 64 + ty*4];
            float4 bv = *(const float4*)&sK[d*SAS + tx*4];
            ull bp0 = pk(bv.x, bv.y), bp1 = pk(bv.z, bv.w);
            float ar[8] = {a0.x,a0.y,a0.z,a0.w, a1.x,a1.y,a1.z,a1.w};
            #pragma unroll
            for (int i = 0; i < 8; i++) {
                ull ap = pk(ar[i], ar[i]);
                fma2(acc2[i][0], ap, bp0);
                fma2(acc2[i][1], ap, bp1);
            }
        }

        // + prev_qk, write qk out, online softmax update
        #pragma unroll
        for (int ri = 0; ri < 8; ri++) {
            int row = (ri >> 2)*64 + ty*4 + (ri & 3);
            int l = l0 + row;
            float q0,q1,q2,q3;
            upk(q0, q1, acc2[ri][0]);
            upk(q2, q3, acc2[ri][1]);
            q0 += pv[ri].x; q1 += pv[ri].y; q2 += pv[ri].z; q3 += pv[ri].w;
            *(float4*)&QKo[(size_t)l*NL + m0 + tx*4] = make_float4(q0, q1, q2, q3);

            float lm = fmaxf(fmaxf(q0, q1), fmaxf(q2, q3));
            #pragma unroll
            for (int off2 = 8; off2; off2 >>= 1)
                lm = fmaxf(lm, __shfl_xor_sync(0xffffffffu, lm, off2));
            float nm = fmaxf(Mx[ri], lm);
            float p0 = __expf(q0 - nm);
            float p1 = __expf(q1 - nm);
            float p2 = __expf(q2 - nm);
            float p3 = __expf(q3 - nm);
            float ls = p0 + p1 + p2 + p3;
            #pragma unroll
            for (int off2 = 8; off2; off2 >>= 1)
                ls += __shfl_xor_sync(0xffffffffu, ls, off2);
            float sc = __expf(Mx[ri] - nm);
            Sx[ri] = Sx[ri]*sc + ls;
            Mx[ri] = nm;
            mul2(O2[ri], O2[ri], pk(sc, sc));
            *(float4*)&sP[row*64 + tx*4] = make_float4(p0, p1, p2, p3);
        }
        __syncthreads();

        // O += P @ V  (f32x2: V pair is the elementwise operand)
        #pragma unroll 4
        for (int mb = 0; mb < 64; mb += 4) {
            float pr[8][4];
            #pragma unroll
            for (int ri = 0; ri < 8; ri++) {
                int row = (ri >> 2)*64 + ty*4 + (ri & 3);
                float4 pvv = *(const float4*)&sP[row*64 + mb];
                pr[ri][0] = pvv.x; pr[ri][1] = pvv.y; pr[ri][2] = pvv.z; pr[ri][3] = pvv.w;
            }
            #pragma unroll
            for (int mm = 0; mm < 4; mm++) {
                ull v2 = *(const ull*)&sV[(mb + mm)*32 + tx*2];
                #pragma unroll
                for (int ri = 0; ri < 8; ri++) {
                    fma2(O2[ri], pk(pr[ri][mm], pr[ri][mm]), v2);
                }
            }
        }
        __syncthreads();
    }

    int b = bh >> 5;
    int c = (bh >> 3) & 3;
    int h = bh & 7;
    #pragma unroll
    for (int ri = 0; ri < 8; ri++) {
        int row = (ri >> 2)*64 + ty*4 + (ri & 3);
        int l = l0 + row;
        int n = b*1024 + l;
        float inv = 1.f / Sx[ri];
        float o0, o1;
        upk(o0, o1, O2[ri]);
        *(float2*)&g_a[((size_t)c*NN + n)*256 + h*32 + tx*2] =
            make_float2(o0*inv, o1*inv);
    }
}

// =================================================================================
// Kernel 5: concat(xh, o) -> inorm2 -> w1 (leaky) -> w2 -> depthwise mix -> +x
// =================================================================================
__global__ void __launch_bounds__(256) k_ffn(
    const float* __restrict__ x,
    const float* __restrict__ g2, const float* __restrict__ b2,
    const float* __restrict__ w1, const float* __restrict__ w2,
    const float* __restrict__ dw, float* __restrict__ hout)
{
    __shared__ float sz[8][256];
    __shared__ float sz1[8][4];
    __shared__ float sredA[8], sredB[8];
    __shared__ float sbc[2];

    int f = threadIdx.x;
    int n = blockIdx.x;
    int b = n >> 10, l = n & 1023;

    float zv[8];
    #pragma unroll
    for (int c = 0; c < 4; c++) {
        zv[c]     = x[((size_t)(b*4 + c)*1024 + l)*256 + f];
        zv[4 + c] = g_o[((size_t)c*NN + n)*256 + f];
    }

    #pragma unroll
    for (int ch = 0; ch < 8; ch++) {
        float v = zv[ch], v2 = v*v;
        #pragma unroll
        for (int off = 16; off; off >>= 1) {
            v  += __shfl_xor_sync(0xffffffffu, v,  off);
            v2 += __shfl_xor_sync(0xffffffffu, v2, off);
        }
        if ((f & 31) == 0) { sredA[f >> 5] = v; sredB[f >> 5] = v2; }
        __syncthreads();
        if (f == 0) {
            float s = 0.f, ss = 0.f;
            #pragma unroll
            for (int w = 0; w < 8; w++) { s += sredA[w]; ss += sredB[w]; }
            sbc[0] = s * (1.f/256.f);
            sbc[1] = ss * (1.f/256.f);
        }
        __syncthreads();
        float mean = sbc[0];
        float var  = sbc[1] - mean*mean;
        sz[ch][f] = (zv[ch] - mean) * rsqrtf(var + 1e-5f) * g2[ch] + b2[ch];
    }
    __syncthreads();

    int w = f >> 5, lane = f & 31;
    float a0 = 0.f, a1 = 0.f, a2 = 0.f, a3 = 0.f;
    #pragma unroll
    for (int k = 0; k < 8; k++) {
        int ff = lane + 32*k;
        float zf = sz[w][ff];
        a0 += zf * w1[(w*4 + 0)*256 + ff];
        a1 += zf * w1[(w*4 + 1)*256 + ff];
        a2 += zf * w1[(w*4 + 2)*256 + ff];
        a3 += zf * w1[(w*4 + 3)*256 + ff];
    }
    #pragma unroll
    for (int off = 16; off; off >>= 1) {
        a0 += __shfl_xor_sync(0xffffffffu, a0, off);
        a1 += __shfl_xor_sync(0xffffffffu, a1, off);
        a2 += __shfl_xor_sync(0xffffffffu, a2, off);
        a3 += __shfl_xor_sync(0xffffffffu, a3, off);
    }
    if (lane == 0) {
        sz1[w][0] = (a0 > 0.f) ? a0 : 0.01f*a0;
        sz1[w][1] = (a1 > 0.f) ? a1 : 0.01f*a1;
        sz1[w][2] = (a2 > 0.f) ? a2 : 0.01f*a2;
        sz1[w][3] = (a3 > 0.f) ? a3 : 0.01f*a3;
    }
    __syncthreads();

    float ho[4] = {0.f, 0.f, 0.f, 0.f};
    #pragma unroll
    for (int c = 0; c < 8; c++) {
        float4 wv = *(const float4*)&w2[((size_t)c*256 + f)*4];
        float z2 = sz1[c][0]*wv.x + sz1[c][1]*wv.y + sz1[c][2]*wv.z + sz1[c][3]*wv.w;
        #pragma unroll
        for (int d = 0; d < 4; d++)
            ho[d] += z2 * dw[d*8 + c];
    }
    #pragma unroll
    for (int d = 0; d < 4; d++) {
        size_t idx = ((size_t)(b*4 + d)*1024 + l)*256 + f;
        hout[idx] = x[idx] + ho[d];
    }
}

// =================================================================================
extern "C" void kernel_launch(void* const* d_in, const int* in_sizes, int n_in,
                              void* d_out, int out_size)
{
    const float* x       = (const float*)d_in[0];
    const float* prev_qk = (const float*)d_in[1];
    const float* g1      = (const float*)d_in[2];
    const float* b1      = (const float*)d_in[3];
    const float* wq_conv = (const float*)d_in[4];
    const float* wk_conv = (const float*)d_in[5];
    const float* wv_conv = (const float*)d_in[6];
    const float* wq_pw   = (const float*)d_in[7];
    const float* wk_pw   = (const float*)d_in[8];
    const float* wv_pw   = (const float*)d_in[9];
    const float* wo_pw   = (const float*)d_in[10];
    const float* g2      = (const float*)d_in[11];
    const float* b2      = (const float*)d_in[12];
    const float* w1_pw   = (const float*)d_in[13];
    const float* w2_pw   = (const float*)d_in[14];
    const float* w2_dw   = (const float*)d_in[15];

    float* out  = (float*)d_out;
    float* qk_o = out + HOUT_SIZE;

    k_norm_conv<<<NN, 256>>>(x, g1, b1, wq_conv, wk_conv, wv_conv);
    k_gemm<<<dim3(16, 2, 12), 256>>>(wq_pw, wk_pw, wv_pw, wo_pw, 0);
    k_attn<<<dim3(8, NBH), 256>>>(prev_qk, qk_o);
    k_gemm<<<dim3(16, 2, 4), 256>>>(wq_pw, wk_pw, wv_pw, wo_pw, 1);
    k_ffn<<<NN, 256>>>(x, g2, b2, w1_pw, w2_pw, w2_dw, out);
}

// round 4
// speedup vs baseline: 1.3815x; 1.2368x over previous
#include <cuda_runtime.h>
#include <cuda_bf16.h>
#include <math.h>

// Problem constants
#define NB 2
#define NC 4
#define NL 1024
#define NF 256
#define NH 8
#define ND 32
#define NN (NB*NL)          // 2048 samples
#define NBH (NB*NC*NH)      // 64 attention slices
#define HOUT_SIZE (NB*NC*NL*NF)  // 2097152

#define SAS  68
#define SAS2 132

typedef unsigned long long ull;
typedef unsigned int u32;

// packed f32x2 helpers
__device__ __forceinline__ ull pk(float lo, float hi) {
    ull r; asm("mov.b64 %0, {%1,%2};" : "=l"(r) : "f"(lo), "f"(hi)); return r;
}
__device__ __forceinline__ void upk(float& lo, float& hi, ull v) {
    asm("mov.b64 {%0,%1}, %2;" : "=f"(lo), "=f"(hi) : "l"(v));
}
__device__ __forceinline__ void fma2(ull& d, ull a, ull b) {
    asm("fma.rn.f32x2 %0, %1, %2, %3;" : "=l"(d) : "l"(a), "l"(b), "l"(d));
}

// bf16 mma helpers
__device__ __forceinline__ void mma16816(float* c, const u32* a, const u32* b) {
    asm volatile("mma.sync.aligned.m16n8k16.row.col.f32.bf16.bf16.f32 "
        "{%0,%1,%2,%3}, {%4,%5,%6,%7}, {%8,%9}, {%0,%1,%2,%3};"
        : "+f"(c[0]), "+f"(c[1]), "+f"(c[2]), "+f"(c[3])
        : "r"(a[0]), "r"(a[1]), "r"(a[2]), "r"(a[3]), "r"(b[0]), "r"(b[1]));
}
__device__ __forceinline__ u32 pk2h(__nv_bfloat16 a, __nv_bfloat16 b) {
    unsigned short ua = *(unsigned short*)&a, ub = *(unsigned short*)&b;
    return (u32)ua | ((u32)ub << 16);
}

// ------------------- scratch -------------------
__device__ float g_conv[3 * NC * NN * NF];
__device__ float g_qh[NBH * NL * ND];
__device__ float g_kh[NBH * NL * ND];
__device__ float g_vh[NBH * NL * ND];
__device__ float g_a [NC * NN * NF];
__device__ float g_o [NC * NN * NF];

#define STORE_T(s, stride, col4, row, v) { \
    s[((col4)+0)*(stride) + (row)] = v.x; \
    s[((col4)+1)*(stride) + (row)] = v.y; \
    s[((col4)+2)*(stride) + (row)] = v.z; \
    s[((col4)+3)*(stride) + (row)] = v.w; }

// =================================================================================
// Kernel 1: instance-norm + 3-tap conv -> g_conv
// =================================================================================
__global__ void __launch_bounds__(256) k_norm_conv(
    const float* __restrict__ x,
    const float* __restrict__ g1, const float* __restrict__ b1,
    const float* __restrict__ wq, const float* __restrict__ wk, const float* __restrict__ wv)
{
    __shared__ float snx[4][256];
    __shared__ float sw[3][4][4][3];
    __shared__ float sredA[8], sredB[8];
    __shared__ float sbc[2];

    int f = threadIdx.x;
    int n = blockIdx.x;
    int b = n >> 10, l = n & 1023;

    if (f < 144) {
        int mat = f / 48, rem = f % 48;
        int o = rem / 12, i = (rem % 12) / 3, kh = rem % 3;
        const float* wsrc = (mat == 0) ? wq : (mat == 1) ? wk : wv;
        sw[mat][o][i][kh] = wsrc[(o*4 + i)*9 + kh*3 + 1];
    }

    float xv[4];
    #pragma unroll
    for (int c = 0; c < 4; c++)
        xv[c] = x[((size_t)(b*4 + c)*1024 + l)*256 + f];

    #pragma unroll
    for (int c = 0; c < 4; c++) {
        float v = xv[c], v2 = v*v;
        #pragma unroll
        for (int off = 16; off; off >>= 1) {
            v  += __shfl_xor_sync(0xffffffffu, v,  off);
            v2 += __shfl_xor_sync(0xffffffffu, v2, off);
        }
        if ((f & 31) == 0) { sredA[f >> 5] = v; sredB[f >> 5] = v2; }
        __syncthreads();
        if (f == 0) {
            float s = 0.f, ss = 0.f;
            #pragma unroll
            for (int w = 0; w < 8; w++) { s += sredA[w]; ss += sredB[w]; }
            sbc[0] = s * (1.f/256.f);
            sbc[1] = ss * (1.f/256.f);
        }
        __syncthreads();
        float mean = sbc[0];
        float var  = sbc[1] - mean*mean;
        float rs   = rsqrtf(var + 1e-5f);
        snx[c][f] = (xv[c] - mean) * rs * g1[c] + b1[c];
    }
    __syncthreads();

    float le[4], ce[4], ri[4];
    #pragma unroll
    for (int i = 0; i < 4; i++) {
        le[i] = (f > 0)   ? snx[i][f-1] : 0.f;
        ce[i] = snx[i][f];
        ri[i] = (f < 255) ? snx[i][f+1] : 0.f;
    }
    #pragma unroll
    for (int mat = 0; mat < 3; mat++) {
        #pragma unroll
        for (int o = 0; o < 4; o++) {
            float acc = 0.f;
            #pragma unroll
            for (int i = 0; i < 4; i++)
                acc += le[i]*sw[mat][o][i][0] + ce[i]*sw[mat][o][i][1] + ri[i]*sw[mat][o][i][2];
            g_conv[((size_t)(mat*4 + o)*NN + n)*256 + f] = acc;
        }
    }
}

// =================================================================================
// Kernel 2/4: per-channel SGEMM (f32x2 path, unchanged)
// =================================================================================
__global__ void __launch_bounds__(256) k_gemm(
    const float* __restrict__ wq, const float* __restrict__ wk,
    const float* __restrict__ wv, const float* __restrict__ wo, int phase)
{
    __shared__ float sA[32*SAS2];
    __shared__ float sB[32*SAS2];

    int t  = threadIdx.x;
    int tx = t & 15, ty = t >> 4;
    int n0 = blockIdx.x * 128;
    int g0 = blockIdx.y * 128;
    int z  = blockIdx.z;

    const float *A, *W;
    int mat, c;
    if (phase == 0) {
        mat = z >> 2; c = z & 3;
        A = g_conv + (size_t)z * NN * 256;
        W = ((mat == 0) ? wq : (mat == 1) ? wk : wv) + (size_t)c * 65536;
    } else {
        mat = 3; c = z;
        A = g_a + (size_t)c * NN * 256;
        W = wo + (size_t)c * 65536;
    }

    int lrow  = t >> 3;
    int lcol4 = (t & 7) * 4;

    float4 pav[4], pbv[4];
    #pragma unroll
    for (int r = 0; r < 4; r++) {
        pav[r] = *(const float4*)&A[(size_t)(n0 + lrow + r*32)*256 + lcol4];
        pbv[r] = *(const float4*)&W[(size_t)(g0 + lrow + r*32)*256 + lcol4];
    }

    ull acc2[8][4];
    #pragma unroll
    for (int i = 0; i < 8; i++)
        #pragma unroll
        for (int j = 0; j < 4; j++) acc2[i][j] = 0ull;

    for (int k0 = 0; k0 < 256; k0 += 32) {
        #pragma unroll
        for (int r = 0; r < 4; r++) {
            int row = lrow + r*32;
            STORE_T(sA, SAS2, lcol4, row, pav[r]);
            STORE_T(sB, SAS2, lcol4, row, pbv[r]);
        }
        __syncthreads();
        if (k0 < 224) {
            #pragma unroll
            for (int r = 0; r < 4; r++) {
                pav[r] = *(const float4*)&A[(size_t)(n0 + lrow + r*32)*256 + k0 + 32 + lcol4];
                pbv[r] = *(const float4*)&W[(size_t)(g0 + lrow + r*32)*256 + k0 + 32 + lcol4];
            }
        }
        #pragma unroll
        for (int k = 0; k < 32; k++) {
            float4 a0 = *(const float4*)&sA[k*SAS2 + ty*4];
            float4 a1 = *(const float4*)&sA[k*SAS2 + 64 + ty*4];
            float4 b0 = *(const float4*)&sB[k*SAS2 + tx*4];
            float4 b1 = *(const float4*)&sB[k*SAS2 + 64 + tx*4];
            ull bp[4] = { pk(b0.x,b0.y), pk(b0.z,b0.w), pk(b1.x,b1.y), pk(b1.z,b1.w) };
            float ar[8] = {a0.x,a0.y,a0.z,a0.w, a1.x,a1.y,a1.z,a1.w};
            #pragma unroll
            for (int i = 0; i < 8; i++) {
                ull ap = pk(ar[i], ar[i]);
                fma2(acc2[i][0], ap, bp[0]);
                fma2(acc2[i][1], ap, bp[1]);
                fma2(acc2[i][2], ap, bp[2]);
                fma2(acc2[i][3], ap, bp[3]);
            }
        }
        __syncthreads();
    }

    if (phase == 1) {
        float* outp = g_o + (size_t)c * NN * 256;
        #pragma unroll
        for (int ii = 0; ii < 2; ii++)
        #pragma unroll
        for (int i = 0; i < 4; i++) {
            int n = n0 + ii*64 + ty*4 + i;
            #pragma unroll
            for (int jj = 0; jj < 2; jj++) {
                float v0,v1,v2,v3;
                upk(v0, v1, acc2[ii*4+i][jj*2+0]);
                upk(v2, v3, acc2[ii*4+i][jj*2+1]);
                *(float4*)&outp[(size_t)n*256 + g0 + jj*64 + tx*4] =
                    make_float4(v0, v1, v2, v3);
            }
        }
    } else {
        float* outp = (mat == 0) ? g_qh : (mat == 1) ? g_kh : g_vh;
        int d = (tx*4) & 31;
        int i0 = d >> 1;
        float inv0 = 0.f, inv1 = 0.f;
        if (mat < 2) {
            inv0 = powf(10000.f, -(float)i0 / 16.f);
            inv1 = powf(10000.f, -(float)(i0 + 1) / 16.f);
        }
        #pragma unroll
        for (int ii = 0; ii < 2; ii++)
        #pragma unroll
        for (int i = 0; i < 4; i++) {
            int n = n0 + ii*64 + ty*4 + i;
            int b = n >> 10, l = n & 1023;
            float c0=1.f, s0=0.f, c1=1.f, s1=0.f;
            if (mat < 2) {
                sincosf((float)l * inv0, &s0, &c0);
                sincosf((float)l * inv1, &s1, &c1);
            }
            #pragma unroll
            for (int jj = 0; jj < 2; jj++) {
                int g = g0 + jj*64 + tx*4;
                int h = g >> 5;
                float v0,v1,v2,v3;
                upk(v0, v1, acc2[ii*4+i][jj*2+0]);
                upk(v2, v3, acc2[ii*4+i][jj*2+1]);
                if (mat < 2) {
                    float r0 = v0*c0 - v1*s0;
                    float r1 = v1*c0 + v0*s0;
                    float r2 = v2*c1 - v3*s1;
                    float r3 = v3*c1 + v2*s1;
                    v0 = r0; v1 = r1; v2 = r2; v3 = r3;
                    if (mat == 0) { v0 *= 0.0625f; v1 *= 0.0625f; v2 *= 0.0625f; v3 *= 0.0625f; }
                }
                size_t oi = (((size_t)(b*4 + c)*8 + h)*1024 + l)*32 + d;
                *(float4*)&outp[oi] = make_float4(v0, v1, v2, v3);
            }
        }
    }
}

// =================================================================================
// Kernel 3: flash attention via mma.sync bf16 with 2-term precision splitting.
// Block: 256 thr (8 warps), tile 128 l-rows x 64 m-cols per step.
// Warp w owns rows 16w..16w+15.  QK: M16N8K16 x (8 nfrag x 2 kstep x 3 split).
// P stays in registers (C-frag == A-frag layout).  PV: 4 nfrag(d) x 4 kstep x 3.
// =================================================================================
#define QS 40   // bf16 row stride for Q tiles (conflict-free frag loads)
#define KS 40   // bf16 row stride for K tiles
#define VS 72   // bf16 row stride for V^T tiles

__global__ void __launch_bounds__(256) k_attn(
    const float* __restrict__ prev_qk, float* __restrict__ qk_out)
{
    __shared__ __nv_bfloat16 sQh[128*QS], sQl[128*QS];
    __shared__ __nv_bfloat16 sKh[64*KS],  sKl[64*KS];
    __shared__ __nv_bfloat16 sVh[32*VS],  sVl[32*VS];

    int t    = threadIdx.x;
    int w    = t >> 5;
    int lane = t & 31;
    int g    = lane >> 2;   // groupID
    int q    = lane & 3;    // threadID in group
    int bh   = blockIdx.y;
    int l0   = blockIdx.x * 128;

    const float* Qp  = g_qh + (size_t)bh * NL * ND;
    const float* Kp  = g_kh + (size_t)bh * NL * ND;
    const float* Vp  = g_vh + (size_t)bh * NL * ND;
    const float* Pp  = prev_qk + (size_t)bh * NL * NL;
    float*       QKo = qk_out  + (size_t)bh * NL * NL;

    // ---- convert Q tile (128 x 32) to bf16 hi/lo ----
    #pragma unroll
    for (int j = 0; j < 16; j++) {
        int idx = t + 256*j;
        int row = idx >> 5, d = idx & 31;
        float qv = Qp[(size_t)(l0 + row)*32 + d];
        __nv_bfloat16 h = __float2bfloat16(qv);
        sQh[row*QS + d] = h;
        sQl[row*QS + d] = __float2bfloat16(qv - __bfloat162float(h));
    }

    float O[4][4];
    #pragma unroll
    for (int i = 0; i < 4; i++)
        #pragma unroll
        for (int j = 0; j < 4; j++) O[i][j] = 0.f;
    float M0 = -1e30f, M1 = -1e30f, S0 = 0.f, S1 = 0.f;

    int rowA = 16*w + g;          // this thread's row pair: rowA, rowA+8
    __syncthreads();

    for (int m0 = 0; m0 < NL; m0 += 64) {
        // ---- convert K, V tiles ----
        #pragma unroll
        for (int j = 0; j < 8; j++) {
            int idx = t + 256*j;
            int m = idx >> 5, d = idx & 31;
            float kv = Kp[(size_t)(m0 + m)*32 + d];
            __nv_bfloat16 kh = __float2bfloat16(kv);
            sKh[m*KS + d] = kh;
            sKl[m*KS + d] = __float2bfloat16(kv - __bfloat162float(kh));
            float vv = Vp[(size_t)(m0 + m)*32 + d];
            __nv_bfloat16 vh = __float2bfloat16(vv);
            sVh[d*VS + m] = vh;
            sVl[d*VS + m] = __float2bfloat16(vv - __bfloat162float(vh));
        }
        __syncthreads();

        // ---- prefetch prev_qk (DRAM) into registers ----
        float2 pv[8][2];
        #pragma unroll
        for (int nf = 0; nf < 8; nf++) {
            #pragma unroll
            for (int rr = 0; rr < 2; rr++) {
                size_t off = (size_t)(l0 + rowA + rr*8)*NL + m0 + nf*8 + 2*q;
                pv[nf][rr] = *(const float2*)&Pp[off];
            }
        }

        // ---- QK^T: 8 nfrags x 2 ksteps x 3 split-terms ----
        float qk[8][4];
        #pragma unroll
        for (int nf = 0; nf < 8; nf++)
            #pragma unroll
            for (int i = 0; i < 4; i++) qk[nf][i] = 0.f;

        #pragma unroll
        for (int ks = 0; ks < 2; ks++) {
            int k0 = ks*16;
            u32 ah[4], al[4];
            ah[0] = *(const u32*)&sQh[(rowA    )*QS + k0 + 2*q];
            ah[1] = *(const u32*)&sQh[(rowA + 8)*QS + k0 + 2*q];
            ah[2] = *(const u32*)&sQh[(rowA    )*QS + k0 + 2*q + 8];
            ah[3] = *(const u32*)&sQh[(rowA + 8)*QS + k0 + 2*q + 8];
            al[0] = *(const u32*)&sQl[(rowA    )*QS + k0 + 2*q];
            al[1] = *(const u32*)&sQl[(rowA + 8)*QS + k0 + 2*q];
            al[2] = *(const u32*)&sQl[(rowA    )*QS + k0 + 2*q + 8];
            al[3] = *(const u32*)&sQl[(rowA + 8)*QS + k0 + 2*q + 8];
            #pragma unroll
            for (int nf = 0; nf < 8; nf++) {
                int mr = nf*8 + g;
                u32 bh_[2], bl_[2];
                bh_[0] = *(const u32*)&sKh[mr*KS + k0 + 2*q];
                bh_[1] = *(const u32*)&sKh[mr*KS + k0 + 2*q + 8];
                bl_[0] = *(const u32*)&sKl[mr*KS + k0 + 2*q];
                bl_[1] = *(const u32*)&sKl[mr*KS + k0 + 2*q + 8];
                mma16816(qk[nf], ah, bh_);
                mma16816(qk[nf], al, bh_);
                mma16816(qk[nf], ah, bl_);
            }
        }

        // ---- add prev, write qk out, softmax ----
        float lm0 = -1e30f, lm1 = -1e30f;
        #pragma unroll
        for (int nf = 0; nf < 8; nf++) {
            qk[nf][0] += pv[nf][0].x; qk[nf][1] += pv[nf][0].y;
            qk[nf][2] += pv[nf][1].x; qk[nf][3] += pv[nf][1].y;
            size_t off0 = (size_t)(l0 + rowA    )*NL + m0 + nf*8 + 2*q;
            size_t off1 = (size_t)(l0 + rowA + 8)*NL + m0 + nf*8 + 2*q;
            *(float2*)&QKo[off0] = make_float2(qk[nf][0], qk[nf][1]);
            *(float2*)&QKo[off1] = make_float2(qk[nf][2], qk[nf][3]);
            lm0 = fmaxf(lm0, fmaxf(qk[nf][0], qk[nf][1]));
            lm1 = fmaxf(lm1, fmaxf(qk[nf][2], qk[nf][3]));
        }
        lm0 = fmaxf(lm0, __shfl_xor_sync(0xffffffffu, lm0, 1));
        lm0 = fmaxf(lm0, __shfl_xor_sync(0xffffffffu, lm0, 2));
        lm1 = fmaxf(lm1, __shfl_xor_sync(0xffffffffu, lm1, 1));
        lm1 = fmaxf(lm1, __shfl_xor_sync(0xffffffffu, lm1, 2));

        float nm0 = fmaxf(M0, lm0), nm1 = fmaxf(M1, lm1);
        float sc0 = __expf(M0 - nm0), sc1 = __expf(M1 - nm1);
        M0 = nm0; M1 = nm1;

        // exp + bf16-split P fragments
        u32 ph01[8], ph23[8], pl01[8], pl23[8];
        float ls0 = 0.f, ls1 = 0.f;
        #pragma unroll
        for (int nf = 0; nf < 8; nf++) {
            float p0 = __expf(qk[nf][0] - nm0);
            float p1 = __expf(qk[nf][1] - nm0);
            float p2 = __expf(qk[nf][2] - nm1);
            float p3 = __expf(qk[nf][3] - nm1);
            ls0 += p0 + p1; ls1 += p2 + p3;
            __nv_bfloat16 h0 = __float2bfloat16(p0);
            __nv_bfloat16 h1 = __float2bfloat16(p1);
            __nv_bfloat16 h2 = __float2bfloat16(p2);
            __nv_bfloat16 h3 = __float2bfloat16(p3);
            ph01[nf] = pk2h(h0, h1);
            ph23[nf] = pk2h(h2, h3);
            pl01[nf] = pk2h(__float2bfloat16(p0 - __bfloat162float(h0)),
                            __float2bfloat16(p1 - __bfloat162float(h1)));
            pl23[nf] = pk2h(__float2bfloat16(p2 - __bfloat162float(h2)),
                            __float2bfloat16(p3 - __bfloat162float(h3)));
        }
        S0 = S0*sc0 + ls0;
        S1 = S1*sc1 + ls1;

        // rescale O
        #pragma unroll
        for (int nf2 = 0; nf2 < 4; nf2++) {
            O[nf2][0] *= sc0; O[nf2][1] *= sc0;
            O[nf2][2] *= sc1; O[nf2][3] *= sc1;
        }

        // ---- PV: 4 ksteps(m) x 4 nfrags(d) x 3 split-terms ----
        #pragma unroll
        for (int ks2 = 0; ks2 < 4; ks2++) {
            u32 pa[4]  = { ph01[2*ks2], ph23[2*ks2], ph01[2*ks2+1], ph23[2*ks2+1] };
            u32 pla[4] = { pl01[2*ks2], pl23[2*ks2], pl01[2*ks2+1], pl23[2*ks2+1] };
            #pragma unroll
            for (int nf2 = 0; nf2 < 4; nf2++) {
                int dr = nf2*8 + g;
                u32 vb[2], vlb[2];
                vb[0]  = *(const u32*)&sVh[dr*VS + ks2*16 + 2*q];
                vb[1]  = *(const u32*)&sVh[dr*VS + ks2*16 + 2*q + 8];
                vlb[0] = *(const u32*)&sVl[dr*VS + ks2*16 + 2*q];
                vlb[1] = *(const u32*)&sVl[dr*VS + ks2*16 + 2*q + 8];
                mma16816(O[nf2], pa,  vb);
                mma16816(O[nf2], pla, vb);
                mma16816(O[nf2], pa,  vlb);
            }
        }
        __syncthreads();
    }

    // merge partial sums across the quad, normalize, store
    S0 += __shfl_xor_sync(0xffffffffu, S0, 1);
    S0 += __shfl_xor_sync(0xffffffffu, S0, 2);
    S1 += __shfl_xor_sync(0xffffffffu, S1, 1);
    S1 += __shfl_xor_sync(0xffffffffu, S1, 2);
    float inv0 = 1.f / S0, inv1 = 1.f / S1;

    int b = bh >> 5;
    int c = (bh >> 3) & 3;
    int h = bh & 7;
    int n0r = b*1024 + l0 + rowA;
    #pragma unroll
    for (int nf2 = 0; nf2 < 4; nf2++) {
        int col = h*32 + nf2*8 + 2*q;
        *(float2*)&g_a[((size_t)c*NN + n0r    )*256 + col] =
            make_float2(O[nf2][0]*inv0, O[nf2][1]*inv0);
        *(float2*)&g_a[((size_t)c*NN + n0r + 8)*256 + col] =
            make_float2(O[nf2][2]*inv1, O[nf2][3]*inv1);
    }
}

// =================================================================================
// Kernel 5: FFN tail
// =================================================================================
__global__ void __launch_bounds__(256) k_ffn(
    const float* __restrict__ x,
    const float* __restrict__ g2, const float* __restrict__ b2,
    const float* __restrict__ w1, const float* __restrict__ w2,
    const float* __restrict__ dw, float* __restrict__ hout)
{
    __shared__ float sz[8][256];
    __shared__ float sz1[8][4];
    __shared__ float sredA[8], sredB[8];
    __shared__ float sbc[2];

    int f = threadIdx.x;
    int n = blockIdx.x;
    int b = n >> 10, l = n & 1023;

    float zv[8];
    #pragma unroll
    for (int c = 0; c < 4; c++) {
        zv[c]     = x[((size_t)(b*4 + c)*1024 + l)*256 + f];
        zv[4 + c] = g_o[((size_t)c*NN + n)*256 + f];
    }

    #pragma unroll
    for (int ch = 0; ch < 8; ch++) {
        float v = zv[ch], v2 = v*v;
        #pragma unroll
        for (int off = 16; off; off >>= 1) {
            v  += __shfl_xor_sync(0xffffffffu, v,  off);
            v2 += __shfl_xor_sync(0xffffffffu, v2, off);
        }
        if ((f & 31) == 0) { sredA[f >> 5] = v; sredB[f >> 5] = v2; }
        __syncthreads();
        if (f == 0) {
            float s = 0.f, ss = 0.f;
            #pragma unroll
            for (int w = 0; w < 8; w++) { s += sredA[w]; ss += sredB[w]; }
            sbc[0] = s * (1.f/256.f);
            sbc[1] = ss * (1.f/256.f);
        }
        __syncthreads();
        float mean = sbc[0];
        float var  = sbc[1] - mean*mean;
        sz[ch][f] = (zv[ch] - mean) * rsqrtf(var + 1e-5f) * g2[ch] + b2[ch];
    }
    __syncthreads();

    int w = f >> 5, lane = f & 31;
    float a0 = 0.f, a1 = 0.f, a2 = 0.f, a3 = 0.f;
    #pragma unroll
    for (int k = 0; k < 8; k++) {
        int ff = lane + 32*k;
        float zf = sz[w][ff];
        a0 += zf * w1[(w*4 + 0)*256 + ff];
        a1 += zf * w1[(w*4 + 1)*256 + ff];
        a2 += zf * w1[(w*4 + 2)*256 + ff];
        a3 += zf * w1[(w*4 + 3)*256 + ff];
    }
    #pragma unroll
    for (int off = 16; off; off >>= 1) {
        a0 += __shfl_xor_sync(0xffffffffu, a0, off);
        a1 += __shfl_xor_sync(0xffffffffu, a1, off);
        a2 += __shfl_xor_sync(0xffffffffu, a2, off);
        a3 += __shfl_xor_sync(0xffffffffu, a3, off);
    }
    if (lane == 0) {
        sz1[w][0] = (a0 > 0.f) ? a0 : 0.01f*a0;
        sz1[w][1] = (a1 > 0.f) ? a1 : 0.01f*a1;
        sz1[w][2] = (a2 > 0.f) ? a2 : 0.01f*a2;
        sz1[w][3] = (a3 > 0.f) ? a3 : 0.01f*a3;
    }
    __syncthreads();

    float ho[4] = {0.f, 0.f, 0.f, 0.f};
    #pragma unroll
    for (int c = 0; c < 8; c++) {
        float4 wv = *(const float4*)&w2[((size_t)c*256 + f)*4];
        float z2 = sz1[c][0]*wv.x + sz1[c][1]*wv.y + sz1[c][2]*wv.z + sz1[c][3]*wv.w;
        #pragma unroll
        for (int d = 0; d < 4; d++)
            ho[d] += z2 * dw[d*8 + c];
    }
    #pragma unroll
    for (int d = 0; d < 4; d++) {
        size_t idx = ((size_t)(b*4 + d)*1024 + l)*256 + f;
        hout[idx] = x[idx] + ho[d];
    }
}

// =================================================================================
extern "C" void kernel_launch(void* const* d_in, const int* in_sizes, int n_in,
                              void* d_out, int out_size)
{
    const float* x       = (const float*)d_in[0];
    const float* prev_qk = (const float*)d_in[1];
    const float* g1      = (const float*)d_in[2];
    const float* b1      = (const float*)d_in[3];
    const float* wq_conv = (const float*)d_in[4];
    const float* wk_conv = (const float*)d_in[5];
    const float* wv_conv = (const float*)d_in[6];
    const float* wq_pw   = (const float*)d_in[7];
    const float* wk_pw   = (const float*)d_in[8];
    const float* wv_pw   = (const float*)d_in[9];
    const float* wo_pw   = (const float*)d_in[10];
    const float* g2      = (const float*)d_in[11];
    const float* b2      = (const float*)d_in[12];
    const float* w1_pw   = (const float*)d_in[13];
    const float* w2_pw   = (const float*)d_in[14];
    const float* w2_dw   = (const float*)d_in[15];

    float* out  = (float*)d_out;
    float* qk_o = out + HOUT_SIZE;

    k_norm_conv<<<NN, 256>>>(x, g1, b1, wq_conv, wk_conv, wv_conv);
    k_gemm<<<dim3(16, 2, 12), 256>>>(wq_pw, wk_pw, wv_pw, wo_pw, 0);
    k_attn<<<dim3(8, NBH), 256>>>(prev_qk, qk_o);
    k_gemm<<<dim3(16, 2, 4), 256>>>(wq_pw, wk_pw, wv_pw, wo_pw, 1);
    k_ffn<<<NN, 256>>>(x, g2, b2, w1_pw, w2_pw, w2_dw, out);
}

// round 5
// speedup vs baseline: 1.7085x; 1.2367x over previous
#include <cuda_runtime.h>
#include <cuda_bf16.h>
#include <math.h>

#define NB 2
#define NC 4
#define NL 1024
#define NF 256
#define NH 8
#define ND 32
#define NN (NB*NL)
#define NBH (NB*NC*NH)
#define HOUT_SIZE (NB*NC*NL*NF)

typedef unsigned int u32;

__device__ __forceinline__ void mma16816(float* c, const u32* a, const u32* b) {
    asm volatile("mma.sync.aligned.m16n8k16.row.col.f32.bf16.bf16.f32 "
        "{%0,%1,%2,%3}, {%4,%5,%6,%7}, {%8,%9}, {%0,%1,%2,%3};"
        : "+f"(c[0]), "+f"(c[1]), "+f"(c[2]), "+f"(c[3])
        : "r"(a[0]), "r"(a[1]), "r"(a[2]), "r"(a[3]), "r"(b[0]), "r"(b[1]));
}
__device__ __forceinline__ u32 pk2h(__nv_bfloat16 a, __nv_bfloat16 b) {
    unsigned short ua = *(unsigned short*)&a, ub = *(unsigned short*)&b;
    return (u32)ua | ((u32)ub << 16);
}
__device__ __forceinline__ u32 s2u(const void* p) {
    return (u32)__cvta_generic_to_shared(p);
}
__device__ __forceinline__ void ldsm4(u32& r0, u32& r1, u32& r2, u32& r3, u32 addr) {
    asm volatile("ldmatrix.sync.aligned.m8n8.x4.shared.b16 {%0,%1,%2,%3}, [%4];"
        : "=r"(r0), "=r"(r1), "=r"(r2), "=r"(r3) : "r"(addr));
}

// ------------------- scratch (bf16 hi/lo interchange) -------------------
__device__ __nv_bfloat16 g_convh[12*NN*NF], g_convl[12*NN*NF];
__device__ __nv_bfloat16 g_wh[16*65536],    g_wl[16*65536];
__device__ __nv_bfloat16 g_qh_h[NBH*NL*ND], g_qh_l[NBH*NL*ND];
__device__ __nv_bfloat16 g_kh_h[NBH*NL*ND], g_kh_l[NBH*NL*ND];
__device__ __nv_bfloat16 g_vT_h[NBH*ND*NL], g_vT_l[NBH*ND*NL];
__device__ __nv_bfloat16 g_ah[NC*NN*NF],    g_al[NC*NN*NF];
__device__ float g_o[NC*NN*NF];
__device__ float g_rcos[NL*16], g_rsin[NL*16];

// =================================================================================
// Tiny prep kernels
// =================================================================================
__global__ void k_rope() {
    int idx = blockIdx.x*256 + threadIdx.x;
    if (idx < NL*16) {
        int l = idx >> 4, i = idx & 15;
        float inv = powf(10000.f, -(float)i / 16.f);
        float s, c;
        sincosf((float)l * inv, &s, &c);
        g_rcos[idx] = c;
        g_rsin[idx] = s;
    }
}

__global__ void k_wsplit(const float* __restrict__ wq, const float* __restrict__ wk,
                         const float* __restrict__ wv, const float* __restrict__ wo) {
    int idx = blockIdx.x*256 + threadIdx.x;     // over 4*262144
    int mat = idx >> 18, rem = idx & 262143;
    const float* src = (mat == 0) ? wq : (mat == 1) ? wk : (mat == 2) ? wv : wo;
    float v = src[rem];
    __nv_bfloat16 h = __float2bfloat16(v);
    g_wh[idx] = h;
    g_wl[idx] = __float2bfloat16(v - __bfloat162float(h));
}

// =================================================================================
// Kernel 1: instance-norm + 3-tap conv -> g_convh/g_convl (bf16 split)
// =================================================================================
__global__ void __launch_bounds__(256) k_norm_conv(
    const float* __restrict__ x,
    const float* __restrict__ g1, const float* __restrict__ b1,
    const float* __restrict__ wq, const float* __restrict__ wk, const float* __restrict__ wv)
{
    __shared__ float snx[4][256];
    __shared__ float sw[3][4][4][3];
    __shared__ float sredA[8], sredB[8];
    __shared__ float sbc[2];

    int f = threadIdx.x;
    int n = blockIdx.x;
    int b = n >> 10, l = n & 1023;

    if (f < 144) {
        int mat = f / 48, rem = f % 48;
        int o = rem / 12, i = (rem % 12) / 3, kh = rem % 3;
        const float* wsrc = (mat == 0) ? wq : (mat == 1) ? wk : wv;
        sw[mat][o][i][kh] = wsrc[(o*4 + i)*9 + kh*3 + 1];
    }

    float xv[4];
    #pragma unroll
    for (int c = 0; c < 4; c++)
        xv[c] = x[((size_t)(b*4 + c)*1024 + l)*256 + f];

    #pragma unroll
    for (int c = 0; c < 4; c++) {
        float v = xv[c], v2 = v*v;
        #pragma unroll
        for (int off = 16; off; off >>= 1) {
            v  += __shfl_xor_sync(0xffffffffu, v,  off);
            v2 += __shfl_xor_sync(0xffffffffu, v2, off);
        }
        if ((f & 31) == 0) { sredA[f >> 5] = v; sredB[f >> 5] = v2; }
        __syncthreads();
        if (f == 0) {
            float s = 0.f, ss = 0.f;
            #pragma unroll
            for (int w = 0; w < 8; w++) { s += sredA[w]; ss += sredB[w]; }
            sbc[0] = s * (1.f/256.f);
            sbc[1] = ss * (1.f/256.f);
        }
        __syncthreads();
        float mean = sbc[0];
        float var  = sbc[1] - mean*mean;
        float rs   = rsqrtf(var + 1e-5f);
        snx[c][f] = (xv[c] - mean) * rs * g1[c] + b1[c];
    }
    __syncthreads();

    float le[4], ce[4], ri[4];
    #pragma unroll
    for (int i = 0; i < 4; i++) {
        le[i] = (f > 0)   ? snx[i][f-1] : 0.f;
        ce[i] = snx[i][f];
        ri[i] = (f < 255) ? snx[i][f+1] : 0.f;
    }
    #pragma unroll
    for (int mat = 0; mat < 3; mat++) {
        #pragma unroll
        for (int o = 0; o < 4; o++) {
            float acc = 0.f;
            #pragma unroll
            for (int i = 0; i < 4; i++)
                acc += le[i]*sw[mat][o][i][0] + ce[i]*sw[mat][o][i][1] + ri[i]*sw[mat][o][i][2];
            size_t oi = ((size_t)(mat*4 + o)*NN + n)*256 + f;
            __nv_bfloat16 h = __float2bfloat16(acc);
            g_convh[oi] = h;
            g_convl[oi] = __float2bfloat16(acc - __bfloat162float(h));
        }
    }
}

// =================================================================================
// Kernel 2/4: split-bf16 mma GEMM.  Y[n][g] = sum_f X[n][f]*W[g][f].
// 128x128x(K=32 chunks), 8 warps (2x4), warp tile 64x32, ldmatrix fragments.
//   phase 0: X = g_convh/l[z], W = g_wh/l[z];  epilogue -> rotary heads (bf16 split)
//   phase 1: X = g_ah/l[c],    W = g_wh/l[12+c]; epilogue -> g_o fp32
// =================================================================================
__global__ void __launch_bounds__(256) k_gemm_mma(int phase)
{
    __shared__ __nv_bfloat16 sXh[128*40], sXl[128*40], sWh[128*40], sWl[128*40];

    int t = threadIdx.x, w = t >> 5, lane = t & 31;
    int g = lane >> 2, q = lane & 3;
    int wr = w >> 2, wc = w & 3;
    int n0 = blockIdx.x * 128, g0 = blockIdx.y * 128, z = blockIdx.z;

    const __nv_bfloat16 *Ah, *Al, *Wh, *Wl;
    int mat, c;
    if (phase == 0) {
        mat = z >> 2; c = z & 3;
        Ah = g_convh + (size_t)z*NN*NF;  Al = g_convl + (size_t)z*NN*NF;
        Wh = g_wh + (size_t)z*65536;     Wl = g_wl + (size_t)z*65536;
    } else {
        mat = 3; c = z;
        Ah = g_ah + (size_t)c*NN*NF;     Al = g_al + (size_t)c*NN*NF;
        Wh = g_wh + (size_t)(12 + c)*65536; Wl = g_wl + (size_t)(12 + c)*65536;
    }

    int laneA = (lane & 15)*40 + (lane >> 4)*8;
    int laneB = (((lane & 16) >> 1) + (lane & 7))*40 + ((lane & 8) ? 8 : 0);
    u32 bXh = s2u(sXh), bXl = s2u(sXl), bWh = s2u(sWh), bWl = s2u(sWl);
    int mrb = wr*64, ncb = wc*32;

    float acc[4][4][4];
    #pragma unroll
    for (int i = 0; i < 4; i++)
        #pragma unroll
        for (int j = 0; j < 4; j++)
            #pragma unroll
            for (int k = 0; k < 4; k++) acc[i][j][k] = 0.f;

    for (int k0 = 0; k0 < 256; k0 += 32) {
        #pragma unroll
        for (int j = 0; j < 2; j++) {
            int idx = t + 256*j;
            int row = idx >> 2, sg = idx & 3;
            size_t so = (size_t)(n0 + row)*256 + k0 + sg*8;
            *(uint4*)&sXh[row*40 + sg*8] = *(const uint4*)&Ah[so];
            *(uint4*)&sXl[row*40 + sg*8] = *(const uint4*)&Al[so];
            size_t wo_ = (size_t)(g0 + row)*256 + k0 + sg*8;
            *(uint4*)&sWh[row*40 + sg*8] = *(const uint4*)&Wh[wo_];
            *(uint4*)&sWl[row*40 + sg*8] = *(const uint4*)&Wl[wo_];
        }
        __syncthreads();

        #pragma unroll
        for (int ks = 0; ks < 2; ks++) {
            int kk = ks*16;
            u32 bhr[4][2], blr[4][2];
            #pragma unroll
            for (int nf2 = 0; nf2 < 2; nf2++) {
                u32 off = (u32)(((ncb + nf2*16)*40 + kk + laneB) * 2);
                ldsm4(bhr[2*nf2][0], bhr[2*nf2][1], bhr[2*nf2+1][0], bhr[2*nf2+1][1], bWh + off);
                ldsm4(blr[2*nf2][0], blr[2*nf2][1], blr[2*nf2+1][0], blr[2*nf2+1][1], bWl + off);
            }
            #pragma unroll
            for (int mf = 0; mf < 4; mf++) {
                u32 off = (u32)(((mrb + mf*16)*40 + kk + laneA) * 2);
                u32 ah[4], al[4];
                ldsm4(ah[0], ah[1], ah[2], ah[3], bXh + off);
                ldsm4(al[0], al[1], al[2], al[3], bXl + off);
                #pragma unroll
                for (int nf = 0; nf < 4; nf++) {
                    mma16816(acc[mf][nf], ah, bhr[nf]);
                    mma16816(acc[mf][nf], al, bhr[nf]);
                    mma16816(acc[mf][nf], ah, blr[nf]);
                }
            }
        }
        __syncthreads();
    }

    if (phase == 1) {
        float* outp = g_o + (size_t)c*NN*NF;
        #pragma unroll
        for (int mf = 0; mf < 4; mf++) {
            #pragma unroll
            for (int rr = 0; rr < 2; rr++) {
                int n = n0 + mrb + mf*16 + g + rr*8;
                #pragma unroll
                for (int nf = 0; nf < 4; nf++) {
                    int gc = g0 + ncb + nf*8 + 2*q;
                    *(float2*)&outp[(size_t)n*256 + gc] =
                        make_float2(acc[mf][nf][2*rr], acc[mf][nf][2*rr+1]);
                }
            }
        }
    } else {
        #pragma unroll
        for (int mf = 0; mf < 4; mf++) {
            #pragma unroll
            for (int rr = 0; rr < 2; rr++) {
                int n = n0 + mrb + mf*16 + g + rr*8;
                int b = n >> 10, l = n & 1023;
                #pragma unroll
                for (int nf = 0; nf < 4; nf++) {
                    int gc = g0 + ncb + nf*8 + 2*q;
                    float v0 = acc[mf][nf][2*rr], v1 = acc[mf][nf][2*rr+1];
                    if (mat < 2) {
                        int i0 = (gc & 31) >> 1;
                        float cs = g_rcos[l*16 + i0], sn = g_rsin[l*16 + i0];
                        float r0 = v0*cs - v1*sn;
                        float r1 = v1*cs + v0*sn;
                        v0 = r0; v1 = r1;
                        if (mat == 0) { v0 *= 0.0625f; v1 *= 0.0625f; }
                    }
                    int h = gc >> 5, d = gc & 31;
                    int bh = (b*4 + c)*8 + h;
                    __nv_bfloat16 h0 = __float2bfloat16(v0);
                    __nv_bfloat16 h1 = __float2bfloat16(v1);
                    __nv_bfloat16 l0b = __float2bfloat16(v0 - __bfloat162float(h0));
                    __nv_bfloat16 l1b = __float2bfloat16(v1 - __bfloat162float(h1));
                    if (mat == 0) {
                        size_t o = ((size_t)bh*1024 + l)*32 + d;
                        *(u32*)&g_qh_h[o] = pk2h(h0, h1);
                        *(u32*)&g_qh_l[o] = pk2h(l0b, l1b);
                    } else if (mat == 1) {
                        size_t o = ((size_t)bh*1024 + l)*32 + d;
                        *(u32*)&g_kh_h[o] = pk2h(h0, h1);
                        *(u32*)&g_kh_l[o] = pk2h(l0b, l1b);
                    } else {
                        size_t o = ((size_t)bh*32 + d)*1024 + l;
                        g_vT_h[o] = h0; g_vT_h[o + 1024] = h1;
                        g_vT_l[o] = l0b; g_vT_l[o + 1024] = l1b;
                    }
                }
            }
        }
    }
}

// =================================================================================
// Kernel 3: flash attention, split-bf16 mma, pure-copy smem staging, ldmatrix.
// =================================================================================
__global__ void __launch_bounds__(256) k_attn(
    const float* __restrict__ prev_qk, float* __restrict__ qk_out)
{
    __shared__ __nv_bfloat16 sQh[128*40], sQl[128*40];
    __shared__ __nv_bfloat16 sKh[64*40],  sKl[64*40];
    __shared__ __nv_bfloat16 sVh[32*72],  sVl[32*72];

    int t = threadIdx.x, w = t >> 5, lane = t & 31;
    int g = lane >> 2, q = lane & 3;
    int bh = blockIdx.y;
    int l0 = blockIdx.x * 128;

    const __nv_bfloat16* Qh = g_qh_h + (size_t)bh*NL*ND;
    const __nv_bfloat16* Ql = g_qh_l + (size_t)bh*NL*ND;
    const __nv_bfloat16* Kh = g_kh_h + (size_t)bh*NL*ND;
    const __nv_bfloat16* Kl = g_kh_l + (size_t)bh*NL*ND;
    const __nv_bfloat16* Vh = g_vT_h + (size_t)bh*ND*NL;
    const __nv_bfloat16* Vl = g_vT_l + (size_t)bh*ND*NL;
    const float* Pp  = prev_qk + (size_t)bh*NL*NL;
    float*       QKo = qk_out  + (size_t)bh*NL*NL;

    // ---- copy Q tile ----
    #pragma unroll
    for (int j = 0; j < 2; j++) {
        int idx = t + 256*j;
        int row = idx >> 2, sg = idx & 3;
        size_t so = (size_t)(l0 + row)*32 + sg*8;
        *(uint4*)&sQh[row*40 + sg*8] = *(const uint4*)&Qh[so];
        *(uint4*)&sQl[row*40 + sg*8] = *(const uint4*)&Ql[so];
    }

    int laneA  = (lane & 15)*40 + (lane >> 4)*8;
    int laneBK = (((lane & 16) >> 1) + (lane & 7))*40 + ((lane & 8) ? 8 : 0);
    int laneBV = (((lane & 16) >> 1) + (lane & 7))*72 + ((lane & 8) ? 8 : 0);
    u32 bQh = s2u(sQh), bQl = s2u(sQl);
    u32 bKh = s2u(sKh), bKl = s2u(sKl);
    u32 bVh = s2u(sVh), bVl = s2u(sVl);

    float O[4][4];
    #pragma unroll
    for (int i = 0; i < 4; i++)
        #pragma unroll
        for (int j = 0; j < 4; j++) O[i][j] = 0.f;
    float M0 = -1e30f, M1 = -1e30f, S0 = 0.f, S1 = 0.f;
    int rowA = 16*w + g;

    for (int m0 = 0; m0 < NL; m0 += 64) {
        // prefetch prev_qk (DRAM) first — longest latency
        float2 pv[8][2];
        #pragma unroll
        for (int nf = 0; nf < 8; nf++) {
            #pragma unroll
            for (int rr = 0; rr < 2; rr++) {
                size_t off = (size_t)(l0 + rowA + rr*8)*NL + m0 + nf*8 + 2*q;
                pv[nf][rr] = *(const float2*)&Pp[off];
            }
        }
        // copy K tile (64x32) and V^T tile (32x64)
        {
            int row = t >> 2, sg = t & 3;
            size_t so = (size_t)(m0 + row)*32 + sg*8;
            *(uint4*)&sKh[row*40 + sg*8] = *(const uint4*)&Kh[so];
            *(uint4*)&sKl[row*40 + sg*8] = *(const uint4*)&Kl[so];
            int d = t >> 3, sg2 = t & 7;
            size_t vo = (size_t)d*NL + m0 + sg2*8;
            *(uint4*)&sVh[d*72 + sg2*8] = *(const uint4*)&Vh[vo];
            *(uint4*)&sVl[d*72 + sg2*8] = *(const uint4*)&Vl[vo];
        }
        __syncthreads();

        // ---- QK^T ----
        float qk[8][4];
        #pragma unroll
        for (int nf = 0; nf < 8; nf++)
            #pragma unroll
            for (int i = 0; i < 4; i++) qk[nf][i] = 0.f;

        #pragma unroll
        for (int ks = 0; ks < 2; ks++) {
            int kk = ks*16;
            u32 aoff = (u32)(((16*w)*40 + kk + laneA) * 2);
            u32 ah[4], al[4];
            ldsm4(ah[0], ah[1], ah[2], ah[3], bQh + aoff);
            ldsm4(al[0], al[1], al[2], al[3], bQl + aoff);
            #pragma unroll
            for (int nf2 = 0; nf2 < 4; nf2++) {
                u32 boff = (u32)(((nf2*16)*40 + kk + laneBK) * 2);
                u32 kb[4], kbl[4];
                ldsm4(kb[0], kb[1], kb[2], kb[3], bKh + boff);
                ldsm4(kbl[0], kbl[1], kbl[2], kbl[3], bKl + boff);
                mma16816(qk[2*nf2],   ah, kb);
                mma16816(qk[2*nf2],   al, kb);
                mma16816(qk[2*nf2],   ah, kbl);
                mma16816(qk[2*nf2+1], ah, kb + 2);
                mma16816(qk[2*nf2+1], al, kb + 2);
                mma16816(qk[2*nf2+1], ah, kbl + 2);
            }
        }

        // ---- add prev, write qk out, softmax ----
        float lm0 = -1e30f, lm1 = -1e30f;
        #pragma unroll
        for (int nf = 0; nf < 8; nf++) {
            qk[nf][0] += pv[nf][0].x; qk[nf][1] += pv[nf][0].y;
            qk[nf][2] += pv[nf][1].x; qk[nf][3] += pv[nf][1].y;
            size_t off0 = (size_t)(l0 + rowA    )*NL + m0 + nf*8 + 2*q;
            size_t off1 = (size_t)(l0 + rowA + 8)*NL + m0 + nf*8 + 2*q;
            *(float2*)&QKo[off0] = make_float2(qk[nf][0], qk[nf][1]);
            *(float2*)&QKo[off1] = make_float2(qk[nf][2], qk[nf][3]);
            lm0 = fmaxf(lm0, fmaxf(qk[nf][0], qk[nf][1]));
            lm1 = fmaxf(lm1, fmaxf(qk[nf][2], qk[nf][3]));
        }
        lm0 = fmaxf(lm0, __shfl_xor_sync(0xffffffffu, lm0, 1));
        lm0 = fmaxf(lm0, __shfl_xor_sync(0xffffffffu, lm0, 2));
        lm1 = fmaxf(lm1, __shfl_xor_sync(0xffffffffu, lm1, 1));
        lm1 = fmaxf(lm1, __shfl_xor_sync(0xffffffffu, lm1, 2));

        float nm0 = fmaxf(M0, lm0), nm1 = fmaxf(M1, lm1);
        float sc0 = __expf(M0 - nm0), sc1 = __expf(M1 - nm1);
        M0 = nm0; M1 = nm1;

        u32 ph01[8], ph23[8], pl01[8], pl23[8];
        float ls0 = 0.f, ls1 = 0.f;
        #pragma unroll
        for (int nf = 0; nf < 8; nf++) {
            float p0 = __expf(qk[nf][0] - nm0);
            float p1 = __expf(qk[nf][1] - nm0);
            float p2 = __expf(qk[nf][2] - nm1);
            float p3 = __expf(qk[nf][3] - nm1);
            ls0 += p0 + p1; ls1 += p2 + p3;
            __nv_bfloat16 h0 = __float2bfloat16(p0);
            __nv_bfloat16 h1 = __float2bfloat16(p1);
            __nv_bfloat16 h2 = __float2bfloat16(p2);
            __nv_bfloat16 h3 = __float2bfloat16(p3);
            ph01[nf] = pk2h(h0, h1);
            ph23[nf] = pk2h(h2, h3);
            pl01[nf] = pk2h(__float2bfloat16(p0 - __bfloat162float(h0)),
                            __float2bfloat16(p1 - __bfloat162float(h1)));
            pl23[nf] = pk2h(__float2bfloat16(p2 - __bfloat162float(h2)),
                            __float2bfloat16(p3 - __bfloat162float(h3)));
        }
        S0 = S0*sc0 + ls0;
        S1 = S1*sc1 + ls1;
        #pragma unroll
        for (int nf2 = 0; nf2 < 4; nf2++) {
            O[nf2][0] *= sc0; O[nf2][1] *= sc0;
            O[nf2][2] *= sc1; O[nf2][3] *= sc1;
        }

        // ---- PV ----
        #pragma unroll
        for (int ks2 = 0; ks2 < 4; ks2++) {
            u32 pa[4]  = { ph01[2*ks2], ph23[2*ks2], ph01[2*ks2+1], ph23[2*ks2+1] };
            u32 pla[4] = { pl01[2*ks2], pl23[2*ks2], pl01[2*ks2+1], pl23[2*ks2+1] };
            #pragma unroll
            for (int p2i = 0; p2i < 2; p2i++) {
                u32 voff = (u32)(((p2i*16)*72 + ks2*16 + laneBV) * 2);
                u32 vb[4], vlb[4];
                ldsm4(vb[0], vb[1], vb[2], vb[3], bVh + voff);
                ldsm4(vlb[0], vlb[1], vlb[2], vlb[3], bVl + voff);
                mma16816(O[2*p2i],   pa,  vb);
                mma16816(O[2*p2i],   pla, vb);
                mma16816(O[2*p2i],   pa,  vlb);
                mma16816(O[2*p2i+1], pa,  vb + 2);
                mma16816(O[2*p2i+1], pla, vb + 2);
                mma16816(O[2*p2i+1], pa,  vlb + 2);
            }
        }
        __syncthreads();
    }

    S0 += __shfl_xor_sync(0xffffffffu, S0, 1);
    S0 += __shfl_xor_sync(0xffffffffu, S0, 2);
    S1 += __shfl_xor_sync(0xffffffffu, S1, 1);
    S1 += __shfl_xor_sync(0xffffffffu, S1, 2);
    float inv0 = 1.f / S0, inv1 = 1.f / S1;

    int b = bh >> 5;
    int c = (bh >> 3) & 3;
    int h = bh & 7;
    int n0r = b*1024 + l0 + rowA;
    #pragma unroll
    for (int nf2 = 0; nf2 < 4; nf2++) {
        int col = h*32 + nf2*8 + 2*q;
        float v0 = O[nf2][0]*inv0, v1 = O[nf2][1]*inv0;
        float v2 = O[nf2][2]*inv1, v3 = O[nf2][3]*inv1;
        __nv_bfloat16 h0 = __float2bfloat16(v0), h1 = __float2bfloat16(v1);
        __nv_bfloat16 h2 = __float2bfloat16(v2), h3 = __float2bfloat16(v3);
        size_t o0 = ((size_t)c*NN + n0r    )*256 + col;
        size_t o1 = ((size_t)c*NN + n0r + 8)*256 + col;
        *(u32*)&g_ah[o0] = pk2h(h0, h1);
        *(u32*)&g_al[o0] = pk2h(__float2bfloat16(v0 - __bfloat162float(h0)),
                                __float2bfloat16(v1 - __bfloat162float(h1)));
        *(u32*)&g_ah[o1] = pk2h(h2, h3);
        *(u32*)&g_al[o1] = pk2h(__float2bfloat16(v2 - __bfloat162float(h2)),
                                __float2bfloat16(v3 - __bfloat162float(h3)));
    }
}

// =================================================================================
// Kernel 5: FFN tail (reads g_o fp32)
// =================================================================================
__global__ void __launch_bounds__(256) k_ffn(
    const float* __restrict__ x,
    const float* __restrict__ g2, const float* __restrict__ b2,
    const float* __restrict__ w1, const float* __restrict__ w2,
    const float* __restrict__ dw, float* __restrict__ hout)
{
    __shared__ float sz[8][256];
    __shared__ float sz1[8][4];
    __shared__ float sredA[8], sredB[8];
    __shared__ float sbc[2];

    int f = threadIdx.x;
    int n = blockIdx.x;
    int b = n >> 10, l = n & 1023;

    float zv[8];
    #pragma unroll
    for (int c = 0; c < 4; c++) {
        zv[c]     = x[((size_t)(b*4 + c)*1024 + l)*256 + f];
        zv[4 + c] = g_o[((size_t)c*NN + n)*256 + f];
    }

    #pragma unroll
    for (int ch = 0; ch < 8; ch++) {
        float v = zv[ch], v2 = v*v;
        #pragma unroll
        for (int off = 16; off; off >>= 1) {
            v  += __shfl_xor_sync(0xffffffffu, v,  off);
            v2 += __shfl_xor_sync(0xffffffffu, v2, off);
        }
        if ((f & 31) == 0) { sredA[f >> 5] = v; sredB[f >> 5] = v2; }
        __syncthreads();
        if (f == 0) {
            float s = 0.f, ss = 0.f;
            #pragma unroll
            for (int w = 0; w < 8; w++) { s += sredA[w]; ss += sredB[w]; }
            sbc[0] = s * (1.f/256.f);
            sbc[1] = ss * (1.f/256.f);
        }
        __syncthreads();
        float mean = sbc[0];
        float var  = sbc[1] - mean*mean;
        sz[ch][f] = (zv[ch] - mean) * rsqrtf(var + 1e-5f) * g2[ch] + b2[ch];
    }
    __syncthreads();

    int w = f >> 5, lane = f & 31;
    float a0 = 0.f, a1 = 0.f, a2 = 0.f, a3 = 0.f;
    #pragma unroll
    for (int k = 0; k < 8; k++) {
        int ff = lane + 32*k;
        float zf = sz[w][ff];
        a0 += zf * w1[(w*4 + 0)*256 + ff];
        a1 += zf * w1[(w*4 + 1)*256 + ff];
        a2 += zf * w1[(w*4 + 2)*256 + ff];
        a3 += zf * w1[(w*4 + 3)*256 + ff];
    }
    #pragma unroll
    for (int off = 16; off; off >>= 1) {
        a0 += __shfl_xor_sync(0xffffffffu, a0, off);
        a1 += __shfl_xor_sync(0xffffffffu, a1, off);
        a2 += __shfl_xor_sync(0xffffffffu, a2, off);
        a3 += __shfl_xor_sync(0xffffffffu, a3, off);
    }
    if (lane == 0) {
        sz1[w][0] = (a0 > 0.f) ? a0 : 0.01f*a0;
        sz1[w][1] = (a1 > 0.f) ? a1 : 0.01f*a1;
        sz1[w][2] = (a2 > 0.f) ? a2 : 0.01f*a2;
        sz1[w][3] = (a3 > 0.f) ? a3 : 0.01f*a3;
    }
    __syncthreads();

    float ho[4] = {0.f, 0.f, 0.f, 0.f};
    #pragma unroll
    for (int c = 0; c < 8; c++) {
        float4 wv = *(const float4*)&w2[((size_t)c*256 + f)*4];
        float z2 = sz1[c][0]*wv.x + sz1[c][1]*wv.y + sz1[c][2]*wv.z + sz1[c][3]*wv.w;
        #pragma unroll
        for (int d = 0; d < 4; d++)
            ho[d] += z2 * dw[d*8 + c];
    }
    #pragma unroll
    for (int d = 0; d < 4; d++) {
        size_t idx = ((size_t)(b*4 + d)*1024 + l)*256 + f;
        hout[idx] = x[idx] + ho[d];
    }
}

// =================================================================================
extern "C" void kernel_launch(void* const* d_in, const int* in_sizes, int n_in,
                              void* d_out, int out_size)
{
    const float* x       = (const float*)d_in[0];
    const float* prev_qk = (const float*)d_in[1];
    const float* g1      = (const float*)d_in[2];
    const float* b1      = (const float*)d_in[3];
    const float* wq_conv = (const float*)d_in[4];
    const float* wk_conv = (const float*)d_in[5];
    const float* wv_conv = (const float*)d_in[6];
    const float* wq_pw   = (const float*)d_in[7];
    const float* wk_pw   = (const float*)d_in[8];
    const float* wv_pw   = (const float*)d_in[9];
    const float* wo_pw   = (const float*)d_in[10];
    const float* g2      = (const float*)d_in[11];
    const float* b2      = (const float*)d_in[12];
    const float* w1_pw   = (const float*)d_in[13];
    const float* w2_pw   = (const float*)d_in[14];
    const float* w2_dw   = (const float*)d_in[15];

    float* out  = (float*)d_out;
    float* qk_o = out + HOUT_SIZE;

    k_wsplit<<<4096, 256>>>(wq_pw, wk_pw, wv_pw, wo_pw);
    k_rope<<<64, 256>>>();
    k_norm_conv<<<NN, 256>>>(x, g1, b1, wq_conv, wk_conv, wv_conv);
    k_gemm_mma<<<dim3(16, 2, 12), 256>>>(0);
    k_attn<<<dim3(8, NBH), 256>>>(prev_qk, qk_o);
    k_gemm_mma<<<dim3(16, 2, 4), 256>>>(1);
    k_ffn<<<NN, 256>>>(x, g2, b2, w1_pw, w2_pw, w2_dw, out);
}

// round 6
// speedup vs baseline: 1.7105x; 1.0012x over previous
#include <cuda_runtime.h>
#include <cuda_bf16.h>
#include <math.h>

#define NB 2
#define NC 4
#define NL 1024
#define NF 256
#define NH 8
#define ND 32
#define NN (NB*NL)
#define NBH (NB*NC*NH)
#define HOUT_SIZE (NB*NC*NL*NF)

typedef unsigned int u32;

__device__ __forceinline__ void mma16816(float* c, const u32* a, const u32* b) {
    asm volatile("mma.sync.aligned.m16n8k16.row.col.f32.bf16.bf16.f32 "
        "{%0,%1,%2,%3}, {%4,%5,%6,%7}, {%8,%9}, {%0,%1,%2,%3};"
        : "+f"(c[0]), "+f"(c[1]), "+f"(c[2]), "+f"(c[3])
        : "r"(a[0]), "r"(a[1]), "r"(a[2]), "r"(a[3]), "r"(b[0]), "r"(b[1]));
}
__device__ __forceinline__ u32 pk2h(__nv_bfloat16 a, __nv_bfloat16 b) {
    unsigned short ua = *(unsigned short*)&a, ub = *(unsigned short*)&b;
    return (u32)ua | ((u32)ub << 16);
}
__device__ __forceinline__ u32 s2u(const void* p) {
    return (u32)__cvta_generic_to_shared(p);
}
__device__ __forceinline__ void ldsm4(u32& r0, u32& r1, u32& r2, u32& r3, u32 addr) {
    asm volatile("ldmatrix.sync.aligned.m8n8.x4.shared.b16 {%0,%1,%2,%3}, [%4];"
        : "=r"(r0), "=r"(r1), "=r"(r2), "=r"(r3) : "r"(addr));
}
__device__ __forceinline__ void cpa16(u32 dst, const void* src) {
    asm volatile("cp.async.cg.shared.global [%0], [%1], 16;" :: "r"(dst), "l"(src));
}
__device__ __forceinline__ void cpa_commit() {
    asm volatile("cp.async.commit_group;");
}

// ------------------- scratch (bf16 hi/lo interchange) -------------------
__device__ __nv_bfloat16 g_convh[12*NN*NF], g_convl[12*NN*NF];
__device__ __nv_bfloat16 g_wh[16*65536],    g_wl[16*65536];
__device__ __nv_bfloat16 g_qh_h[NBH*NL*ND], g_qh_l[NBH*NL*ND];
__device__ __nv_bfloat16 g_kh_h[NBH*NL*ND], g_kh_l[NBH*NL*ND];
__device__ __nv_bfloat16 g_vT_h[NBH*ND*NL], g_vT_l[NBH*ND*NL];
__device__ __nv_bfloat16 g_ah[NC*NN*NF],    g_al[NC*NN*NF];
__device__ float g_o[NC*NN*NF];
__device__ float g_rcos[NL*16], g_rsin[NL*16];

// =================================================================================
// prep: weight split (blocks 0..4095) + rope tables (blocks 4096..4159)
// =================================================================================
__global__ void k_prep(const float* __restrict__ wq, const float* __restrict__ wk,
                       const float* __restrict__ wv, const float* __restrict__ wo) {
    int bidx = blockIdx.x;
    if (bidx < 4096) {
        int idx = bidx*256 + threadIdx.x;
        int mat = idx >> 18, rem = idx & 262143;
        const float* src = (mat == 0) ? wq : (mat == 1) ? wk : (mat == 2) ? wv : wo;
        float v = src[rem];
        __nv_bfloat16 h = __float2bfloat16(v);
        g_wh[idx] = h;
        g_wl[idx] = __float2bfloat16(v - __bfloat162float(h));
    } else {
        int idx = (bidx - 4096)*256 + threadIdx.x;
        if (idx < NL*16) {
            int l = idx >> 4, i = idx & 15;
            float inv = powf(10000.f, -(float)i / 16.f);
            float s, c;
            sincosf((float)l * inv, &s, &c);
            g_rcos[idx] = c;
            g_rsin[idx] = s;
        }
    }
}

// =================================================================================
// Kernel 1: instance-norm + 3-tap conv -> g_convh/g_convl (bf16 split)
// =================================================================================
__global__ void __launch_bounds__(256) k_norm_conv(
    const float* __restrict__ x,
    const float* __restrict__ g1, const float* __restrict__ b1,
    const float* __restrict__ wq, const float* __restrict__ wk, const float* __restrict__ wv)
{
    __shared__ float snx[4][256];
    __shared__ float sw[3][4][4][3];
    __shared__ float sredA[8], sredB[8];
    __shared__ float sbc[2];

    int f = threadIdx.x;
    int n = blockIdx.x;
    int b = n >> 10, l = n & 1023;

    if (f < 144) {
        int mat = f / 48, rem = f % 48;
        int o = rem / 12, i = (rem % 12) / 3, kh = rem % 3;
        const float* wsrc = (mat == 0) ? wq : (mat == 1) ? wk : wv;
        sw[mat][o][i][kh] = wsrc[(o*4 + i)*9 + kh*3 + 1];
    }

    float xv[4];
    #pragma unroll
    for (int c = 0; c < 4; c++)
        xv[c] = x[((size_t)(b*4 + c)*1024 + l)*256 + f];

    #pragma unroll
    for (int c = 0; c < 4; c++) {
        float v = xv[c], v2 = v*v;
        #pragma unroll
        for (int off = 16; off; off >>= 1) {
            v  += __shfl_xor_sync(0xffffffffu, v,  off);
            v2 += __shfl_xor_sync(0xffffffffu, v2, off);
        }
        if ((f & 31) == 0) { sredA[f >> 5] = v; sredB[f >> 5] = v2; }
        __syncthreads();
        if (f == 0) {
            float s = 0.f, ss = 0.f;
            #pragma unroll
            for (int w = 0; w < 8; w++) { s += sredA[w]; ss += sredB[w]; }
            sbc[0] = s * (1.f/256.f);
            sbc[1] = ss * (1.f/256.f);
        }
        __syncthreads();
        float mean = sbc[0];
        float var  = sbc[1] - mean*mean;
        float rs   = rsqrtf(var + 1e-5f);
        snx[c][f] = (xv[c] - mean) * rs * g1[c] + b1[c];
    }
    __syncthreads();

    float le[4], ce[4], ri[4];
    #pragma unroll
    for (int i = 0; i < 4; i++) {
        le[i] = (f > 0)   ? snx[i][f-1] : 0.f;
        ce[i] = snx[i][f];
        ri[i] = (f < 255) ? snx[i][f+1] : 0.f;
    }
    #pragma unroll
    for (int mat = 0; mat < 3; mat++) {
        #pragma unroll
        for (int o = 0; o < 4; o++) {
            float acc = 0.f;
            #pragma unroll
            for (int i = 0; i < 4; i++)
                acc += le[i]*sw[mat][o][i][0] + ce[i]*sw[mat][o][i][1] + ri[i]*sw[mat][o][i][2];
            size_t oi = ((size_t)(mat*4 + o)*NN + n)*256 + f;
            __nv_bfloat16 h = __float2bfloat16(acc);
            g_convh[oi] = h;
            g_convl[oi] = __float2bfloat16(acc - __bfloat162float(h));
        }
    }
}

// =================================================================================
// Kernel 2/4: split-bf16 mma GEMM with 2-stage cp.async pipeline.
// 128x128 tiles, K-chunks of 32.  Dynamic smem: 2 stages x {Xh,Xl,Wh,Wl} x 128*40.
// =================================================================================
#define GSTG (128*40)

__global__ void __launch_bounds__(256) k_gemm_mma(int phase)
{
    extern __shared__ __nv_bfloat16 smem[];
    __nv_bfloat16* sXh = smem;
    __nv_bfloat16* sXl = smem + 2*GSTG;
    __nv_bfloat16* sWh = smem + 4*GSTG;
    __nv_bfloat16* sWl = smem + 6*GSTG;

    int t = threadIdx.x, w = t >> 5, lane = t & 31;
    int g = lane >> 2, q = lane & 3;
    int wr = w >> 2, wc = w & 3;
    int n0 = blockIdx.x * 128, g0 = blockIdx.y * 128, z = blockIdx.z;

    const __nv_bfloat16 *Ah, *Al, *Wh, *Wl;
    int mat, c;
    if (phase == 0) {
        mat = z >> 2; c = z & 3;
        Ah = g_convh + (size_t)z*NN*NF;  Al = g_convl + (size_t)z*NN*NF;
        Wh = g_wh + (size_t)z*65536;     Wl = g_wl + (size_t)z*65536;
    } else {
        mat = 3; c = z;
        Ah = g_ah + (size_t)c*NN*NF;     Al = g_al + (size_t)c*NN*NF;
        Wh = g_wh + (size_t)(12 + c)*65536; Wl = g_wl + (size_t)(12 + c)*65536;
    }

    u32 bXh = s2u(sXh), bXl = s2u(sXl), bWh = s2u(sWh), bWl = s2u(sWl);

    // loader lanes: 512 rows-of-8 per tile; each thread does 2
    int lr0 = t >> 2, lg0 = t & 3;           // row 0..63, seg
    // chunk loader
    #define LOAD_CHUNK(cidx, stg) { \
        int k0_ = (cidx)*32; \
        u32 so_ = (u32)((stg)*GSTG*2); \
        _Pragma("unroll") \
        for (int j = 0; j < 2; j++) { \
            int row = lr0 + j*64, sg = lg0; \
            u32 d_ = (u32)((row*40 + sg*8)*2) + so_; \
            size_t ga = (size_t)(n0 + row)*256 + k0_ + sg*8; \
            size_t gb = (size_t)(g0 + row)*256 + k0_ + sg*8; \
            cpa16(bXh + d_, &Ah[ga]); \
            cpa16(bXl + d_, &Al[ga]); \
            cpa16(bWh + d_, &Wh[gb]); \
            cpa16(bWl + d_, &Wl[gb]); \
        } \
        cpa_commit(); }

    int laneA = (lane & 15)*40 + (lane >> 4)*8;
    int laneB = (((lane & 16) >> 1) + (lane & 7))*40 + ((lane & 8) ? 8 : 0);
    int mrb = wr*64, ncb = wc*32;

    float acc[4][4][4];
    #pragma unroll
    for (int i = 0; i < 4; i++)
        #pragma unroll
        for (int j = 0; j < 4; j++)
            #pragma unroll
            for (int k = 0; k < 4; k++) acc[i][j][k] = 0.f;

    LOAD_CHUNK(0, 0);

    for (int cix = 0; cix < 8; cix++) {
        int s = cix & 1;
        if (cix < 7) {
            LOAD_CHUNK(cix + 1, s ^ 1);
            asm volatile("cp.async.wait_group 1;");
        } else {
            asm volatile("cp.async.wait_group 0;");
        }
        __syncthreads();

        u32 soff = (u32)(s*GSTG*2);
        #pragma unroll
        for (int ks = 0; ks < 2; ks++) {
            int kk = ks*16;
            u32 bhr[4][2], blr[4][2];
            #pragma unroll
            for (int nf2 = 0; nf2 < 2; nf2++) {
                u32 off = (u32)(((ncb + nf2*16)*40 + kk + laneB) * 2) + soff;
                ldsm4(bhr[2*nf2][0], bhr[2*nf2][1], bhr[2*nf2+1][0], bhr[2*nf2+1][1], bWh + off);
                ldsm4(blr[2*nf2][0], blr[2*nf2][1], blr[2*nf2+1][0], blr[2*nf2+1][1], bWl + off);
            }
            #pragma unroll
            for (int mf = 0; mf < 4; mf++) {
                u32 off = (u32)(((mrb + mf*16)*40 + kk + laneA) * 2) + soff;
                u32 ah[4], al[4];
                ldsm4(ah[0], ah[1], ah[2], ah[3], bXh + off);
                ldsm4(al[0], al[1], al[2], al[3], bXl + off);
                #pragma unroll
                for (int nf = 0; nf < 4; nf++) {
                    mma16816(acc[mf][nf], ah, bhr[nf]);
                    mma16816(acc[mf][nf], al, bhr[nf]);
                    mma16816(acc[mf][nf], ah, blr[nf]);
                }
            }
        }
        __syncthreads();
    }

    if (phase == 1) {
        float* outp = g_o + (size_t)c*NN*NF;
        #pragma unroll
        for (int mf = 0; mf < 4; mf++) {
            #pragma unroll
            for (int rr = 0; rr < 2; rr++) {
                int n = n0 + mrb + mf*16 + g + rr*8;
                #pragma unroll
                for (int nf = 0; nf < 4; nf++) {
                    int gc = g0 + ncb + nf*8 + 2*q;
                    *(float2*)&outp[(size_t)n*256 + gc] =
                        make_float2(acc[mf][nf][2*rr], acc[mf][nf][2*rr+1]);
                }
            }
        }
    } else {
        #pragma unroll
        for (int mf = 0; mf < 4; mf++) {
            #pragma unroll
            for (int rr = 0; rr < 2; rr++) {
                int n = n0 + mrb + mf*16 + g + rr*8;
                int b = n >> 10, l = n & 1023;
                #pragma unroll
                for (int nf = 0; nf < 4; nf++) {
                    int gc = g0 + ncb + nf*8 + 2*q;
                    float v0 = acc[mf][nf][2*rr], v1 = acc[mf][nf][2*rr+1];
                    if (mat < 2) {
                        int i0 = (gc & 31) >> 1;
                        float cs = g_rcos[l*16 + i0], sn = g_rsin[l*16 + i0];
                        float r0 = v0*cs - v1*sn;
                        float r1 = v1*cs + v0*sn;
                        v0 = r0; v1 = r1;
                        if (mat == 0) { v0 *= 0.0625f; v1 *= 0.0625f; }
                    }
                    int h = gc >> 5, d = gc & 31;
                    int bh = (b*4 + c)*8 + h;
                    __nv_bfloat16 h0 = __float2bfloat16(v0);
                    __nv_bfloat16 h1 = __float2bfloat16(v1);
                    __nv_bfloat16 l0b = __float2bfloat16(v0 - __bfloat162float(h0));
                    __nv_bfloat16 l1b = __float2bfloat16(v1 - __bfloat162float(h1));
                    if (mat == 0) {
                        size_t o = ((size_t)bh*1024 + l)*32 + d;
                        *(u32*)&g_qh_h[o] = pk2h(h0, h1);
                        *(u32*)&g_qh_l[o] = pk2h(l0b, l1b);
                    } else if (mat == 1) {
                        size_t o = ((size_t)bh*1024 + l)*32 + d;
                        *(u32*)&g_kh_h[o] = pk2h(h0, h1);
                        *(u32*)&g_kh_l[o] = pk2h(l0b, l1b);
                    } else {
                        size_t o = ((size_t)bh*32 + d)*1024 + l;
                        g_vT_h[o] = h0; g_vT_h[o + 1024] = h1;
                        g_vT_l[o] = l0b; g_vT_l[o + 1024] = l1b;
                    }
                }
            }
        }
    }
}

// =================================================================================
// Kernel 3: flash attention, split-bf16 mma (unchanged from R5)
// =================================================================================
__global__ void __launch_bounds__(256) k_attn(
    const float* __restrict__ prev_qk, float* __restrict__ qk_out)
{
    __shared__ __nv_bfloat16 sQh[128*40], sQl[128*40];
    __shared__ __nv_bfloat16 sKh[64*40],  sKl[64*40];
    __shared__ __nv_bfloat16 sVh[32*72],  sVl[32*72];

    int t = threadIdx.x, w = t >> 5, lane = t & 31;
    int g = lane >> 2, q = lane & 3;
    int bh = blockIdx.y;
    int l0 = blockIdx.x * 128;

    const __nv_bfloat16* Qh = g_qh_h + (size_t)bh*NL*ND;
    const __nv_bfloat16* Ql = g_qh_l + (size_t)bh*NL*ND;
    const __nv_bfloat16* Kh = g_kh_h + (size_t)bh*NL*ND;
    const __nv_bfloat16* Kl = g_kh_l + (size_t)bh*NL*ND;
    const __nv_bfloat16* Vh = g_vT_h + (size_t)bh*ND*NL;
    const __nv_bfloat16* Vl = g_vT_l + (size_t)bh*ND*NL;
    const float* Pp  = prev_qk + (size_t)bh*NL*NL;
    float*       QKo = qk_out  + (size_t)bh*NL*NL;

    #pragma unroll
    for (int j = 0; j < 2; j++) {
        int idx = t + 256*j;
        int row = idx >> 2, sg = idx & 3;
        size_t so = (size_t)(l0 + row)*32 + sg*8;
        *(uint4*)&sQh[row*40 + sg*8] = *(const uint4*)&Qh[so];
        *(uint4*)&sQl[row*40 + sg*8] = *(const uint4*)&Ql[so];
    }

    int laneA  = (lane & 15)*40 + (lane >> 4)*8;
    int laneBK = (((lane & 16) >> 1) + (lane & 7))*40 + ((lane & 8) ? 8 : 0);
    int laneBV = (((lane & 16) >> 1) + (lane & 7))*72 + ((lane & 8) ? 8 : 0);
    u32 bQh = s2u(sQh), bQl = s2u(sQl);
    u32 bKh = s2u(sKh), bKl = s2u(sKl);
    u32 bVh = s2u(sVh), bVl = s2u(sVl);

    float O[4][4];
    #pragma unroll
    for (int i = 0; i < 4; i++)
        #pragma unroll
        for (int j = 0; j < 4; j++) O[i][j] = 0.f;
    float M0 = -1e30f, M1 = -1e30f, S0 = 0.f, S1 = 0.f;
    int rowA = 16*w + g;

    for (int m0 = 0; m0 < NL; m0 += 64) {
        float2 pv[8][2];
        #pragma unroll
        for (int nf = 0; nf < 8; nf++) {
            #pragma unroll
            for (int rr = 0; rr < 2; rr++) {
                size_t off = (size_t)(l0 + rowA + rr*8)*NL + m0 + nf*8 + 2*q;
                pv[nf][rr] = *(const float2*)&Pp[off];
            }
        }
        {
            int row = t >> 2, sg = t & 3;
            size_t so = (size_t)(m0 + row)*32 + sg*8;
            *(uint4*)&sKh[row*40 + sg*8] = *(const uint4*)&Kh[so];
            *(uint4*)&sKl[row*40 + sg*8] = *(const uint4*)&Kl[so];
            int d = t >> 3, sg2 = t & 7;
            size_t vo = (size_t)d*NL + m0 + sg2*8;
            *(uint4*)&sVh[d*72 + sg2*8] = *(const uint4*)&Vh[vo];
            *(uint4*)&sVl[d*72 + sg2*8] = *(const uint4*)&Vl[vo];
        }
        __syncthreads();

        float qk[8][4];
        #pragma unroll
        for (int nf = 0; nf < 8; nf++)
            #pragma unroll
            for (int i = 0; i < 4; i++) qk[nf][i] = 0.f;

        #pragma unroll
        for (int ks = 0; ks < 2; ks++) {
            int kk = ks*16;
            u32 aoff = (u32)(((16*w)*40 + kk + laneA) * 2);
            u32 ah[4], al[4];
            ldsm4(ah[0], ah[1], ah[2], ah[3], bQh + aoff);
            ldsm4(al[0], al[1], al[2], al[3], bQl + aoff);
            #pragma unroll
            for (int nf2 = 0; nf2 < 4; nf2++) {
                u32 boff = (u32)(((nf2*16)*40 + kk + laneBK) * 2);
                u32 kb[4], kbl[4];
                ldsm4(kb[0], kb[1], kb[2], kb[3], bKh + boff);
                ldsm4(kbl[0], kbl[1], kbl[2], kbl[3], bKl + boff);
                mma16816(qk[2*nf2],   ah, kb);
                mma16816(qk[2*nf2],   al, kb);
                mma16816(qk[2*nf2],   ah, kbl);
                mma16816(qk[2*nf2+1], ah, kb + 2);
                mma16816(qk[2*nf2+1], al, kb + 2);
                mma16816(qk[2*nf2+1], ah, kbl + 2);
            }
        }

        float lm0 = -1e30f, lm1 = -1e30f;
        #pragma unroll
        for (int nf = 0; nf < 8; nf++) {
            qk[nf][0] += pv[nf][0].x; qk[nf][1] += pv[nf][0].y;
            qk[nf][2] += pv[nf][1].x; qk[nf][3] += pv[nf][1].y;
            size_t off0 = (size_t)(l0 + rowA    )*NL + m0 + nf*8 + 2*q;
            size_t off1 = (size_t)(l0 + rowA + 8)*NL + m0 + nf*8 + 2*q;
            *(float2*)&QKo[off0] = make_float2(qk[nf][0], qk[nf][1]);
            *(float2*)&QKo[off1] = make_float2(qk[nf][2], qk[nf][3]);
            lm0 = fmaxf(lm0, fmaxf(qk[nf][0], qk[nf][1]));
            lm1 = fmaxf(lm1, fmaxf(qk[nf][2], qk[nf][3]));
        }
        lm0 = fmaxf(lm0, __shfl_xor_sync(0xffffffffu, lm0, 1));
        lm0 = fmaxf(lm0, __shfl_xor_sync(0xffffffffu, lm0, 2));
        lm1 = fmaxf(lm1, __shfl_xor_sync(0xffffffffu, lm1, 1));
        lm1 = fmaxf(lm1, __shfl_xor_sync(0xffffffffu, lm1, 2));

        float nm0 = fmaxf(M0, lm0), nm1 = fmaxf(M1, lm1);
        float sc0 = __expf(M0 - nm0), sc1 = __expf(M1 - nm1);
        M0 = nm0; M1 = nm1;

        u32 ph01[8], ph23[8], pl01[8], pl23[8];
        float ls0 = 0.f, ls1 = 0.f;
        #pragma unroll
        for (int nf = 0; nf < 8; nf++) {
            float p0 = __expf(qk[nf][0] - nm0);
            float p1 = __expf(qk[nf][1] - nm0);
            float p2 = __expf(qk[nf][2] - nm1);
            float p3 = __expf(qk[nf][3] - nm1);
            ls0 += p0 + p1; ls1 += p2 + p3;
            __nv_bfloat16 h0 = __float2bfloat16(p0);
            __nv_bfloat16 h1 = __float2bfloat16(p1);
            __nv_bfloat16 h2 = __float2bfloat16(p2);
            __nv_bfloat16 h3 = __float2bfloat16(p3);
            ph01[nf] = pk2h(h0, h1);
            ph23[nf] = pk2h(h2, h3);
            pl01[nf] = pk2h(__float2bfloat16(p0 - __bfloat162float(h0)),
                            __float2bfloat16(p1 - __bfloat162float(h1)));
            pl23[nf] = pk2h(__float2bfloat16(p2 - __bfloat162float(h2)),
                            __float2bfloat16(p3 - __bfloat162float(h3)));
        }
        S0 = S0*sc0 + ls0;
        S1 = S1*sc1 + ls1;
        #pragma unroll
        for (int nf2 = 0; nf2 < 4; nf2++) {
            O[nf2][0] *= sc0; O[nf2][1] *= sc0;
            O[nf2][2] *= sc1; O[nf2][3] *= sc1;
        }

        #pragma unroll
        for (int ks2 = 0; ks2 < 4; ks2++) {
            u32 pa[4]  = { ph01[2*ks2], ph23[2*ks2], ph01[2*ks2+1], ph23[2*ks2+1] };
            u32 pla[4] = { pl01[2*ks2], pl23[2*ks2], pl01[2*ks2+1], pl23[2*ks2+1] };
            #pragma unroll
            for (int p2i = 0; p2i < 2; p2i++) {
                u32 voff = (u32)(((p2i*16)*72 + ks2*16 + laneBV) * 2);
                u32 vb[4], vlb[4];
                ldsm4(vb[0], vb[1], vb[2], vb[3], bVh + voff);
                ldsm4(vlb[0], vlb[1], vlb[2], vlb[3], bVl + voff);
                mma16816(O[2*p2i],   pa,  vb);
                mma16816(O[2*p2i],   pla, vb);
                mma16816(O[2*p2i],   pa,  vlb);
                mma16816(O[2*p2i+1], pa,  vb + 2);
                mma16816(O[2*p2i+1], pla, vb + 2);
                mma16816(O[2*p2i+1], pa,  vlb + 2);
            }
        }
        __syncthreads();
    }

    S0 += __shfl_xor_sync(0xffffffffu, S0, 1);
    S0 += __shfl_xor_sync(0xffffffffu, S0, 2);
    S1 += __shfl_xor_sync(0xffffffffu, S1, 1);
    S1 += __shfl_xor_sync(0xffffffffu, S1, 2);
    float inv0 = 1.f / S0, inv1 = 1.f / S1;

    int b = bh >> 5;
    int c = (bh >> 3) & 3;
    int h = bh & 7;
    int n0r = b*1024 + l0 + rowA;
    #pragma unroll
    for (int nf2 = 0; nf2 < 4; nf2++) {
        int col = h*32 + nf2*8 + 2*q;
        float v0 = O[nf2][0]*inv0, v1 = O[nf2][1]*inv0;
        float v2 = O[nf2][2]*inv1, v3 = O[nf2][3]*inv1;
        __nv_bfloat16 h0 = __float2bfloat16(v0), h1 = __float2bfloat16(v1);
        __nv_bfloat16 h2 = __float2bfloat16(v2), h3 = __float2bfloat16(v3);
        size_t o0 = ((size_t)c*NN + n0r    )*256 + col;
        size_t o1 = ((size_t)c*NN + n0r + 8)*256 + col;
        *(u32*)&g_ah[o0] = pk2h(h0, h1);
        *(u32*)&g_al[o0] = pk2h(__float2bfloat16(v0 - __bfloat162float(h0)),
                                __float2bfloat16(v1 - __bfloat162float(h1)));
        *(u32*)&g_ah[o1] = pk2h(h2, h3);
        *(u32*)&g_al[o1] = pk2h(__float2bfloat16(v2 - __bfloat162float(h2)),
                                __float2bfloat16(v3 - __bfloat162float(h3)));
    }
}

// =================================================================================
// Kernel 5: FFN tail
// =================================================================================
__global__ void __launch_bounds__(256) k_ffn(
    const float* __restrict__ x,
    const float* __restrict__ g2, const float* __restrict__ b2,
    const float* __restrict__ w1, const float* __restrict__ w2,
    const float* __restrict__ dw, float* __restrict__ hout)
{
    __shared__ float sz[8][256];
    __shared__ float sz1[8][4];
    __shared__ float sredA[8], sredB[8];
    __shared__ float sbc[2];

    int f = threadIdx.x;
    int n = blockIdx.x;
    int b = n >> 10, l = n & 1023;

    float zv[8];
    #pragma unroll
    for (int c = 0; c < 4; c++) {
        zv[c]     = x[((size_t)(b*4 + c)*1024 + l)*256 + f];
        zv[4 + c] = g_o[((size_t)c*NN + n)*256 + f];
    }

    #pragma unroll
    for (int ch = 0; ch < 8; ch++) {
        float v = zv[ch], v2 = v*v;
        #pragma unroll
        for (int off = 16; off; off >>= 1) {
            v  += __shfl_xor_sync(0xffffffffu, v,  off);
            v2 += __shfl_xor_sync(0xffffffffu, v2, off);
        }
        if ((f & 31) == 0) { sredA[f >> 5] = v; sredB[f >> 5] = v2; }
        __syncthreads();
        if (f == 0) {
            float s = 0.f, ss = 0.f;
            #pragma unroll
            for (int w = 0; w < 8; w++) { s += sredA[w]; ss += sredB[w]; }
            sbc[0] = s * (1.f/256.f);
            sbc[1] = ss * (1.f/256.f);
        }
        __syncthreads();
        float mean = sbc[0];
        float var  = sbc[1] - mean*mean;
        sz[ch][f] = (zv[ch] - mean) * rsqrtf(var + 1e-5f) * g2[ch] + b2[ch];
    }
    __syncthreads();

    int w = f >> 5, lane = f & 31;
    float a0 = 0.f, a1 = 0.f, a2 = 0.f, a3 = 0.f;
    #pragma unroll
    for (int k = 0; k < 8; k++) {
        int ff = lane + 32*k;
        float zf = sz[w][ff];
        a0 += zf * w1[(w*4 + 0)*256 + ff];
        a1 += zf * w1[(w*4 + 1)*256 + ff];
        a2 += zf * w1[(w*4 + 2)*256 + ff];
        a3 += zf * w1[(w*4 + 3)*256 + ff];
    }
    #pragma unroll
    for (int off = 16; off; off >>= 1) {
        a0 += __shfl_xor_sync(0xffffffffu, a0, off);
        a1 += __shfl_xor_sync(0xffffffffu, a1, off);
        a2 += __shfl_xor_sync(0xffffffffu, a2, off);
        a3 += __shfl_xor_sync(0xffffffffu, a3, off);
    }
    if (lane == 0) {
        sz1[w][0] = (a0 > 0.f) ? a0 : 0.01f*a0;
        sz1[w][1] = (a1 > 0.f) ? a1 : 0.01f*a1;
        sz1[w][2] = (a2 > 0.f) ? a2 : 0.01f*a2;
        sz1[w][3] = (a3 > 0.f) ? a3 : 0.01f*a3;
    }
    __syncthreads();

    float ho[4] = {0.f, 0.f, 0.f, 0.f};
    #pragma unroll
    for (int c = 0; c < 8; c++) {
        float4 wv = *(const float4*)&w2[((size_t)c*256 + f)*4];
        float z2 = sz1[c][0]*wv.x + sz1[c][1]*wv.y + sz1[c][2]*wv.z + sz1[c][3]*wv.w;
        #pragma unroll
        for (int d = 0; d < 4; d++)
            ho[d] += z2 * dw[d*8 + c];
    }
    #pragma unroll
    for (int d = 0; d < 4; d++) {
        size_t idx = ((size_t)(b*4 + d)*1024 + l)*256 + f;
        hout[idx] = x[idx] + ho[d];
    }
}

// =================================================================================
extern "C" void kernel_launch(void* const* d_in, const int* in_sizes, int n_in,
                              void* d_out, int out_size)
{
    const float* x       = (const float*)d_in[0];
    const float* prev_qk = (const float*)d_in[1];
    const float* g1      = (const float*)d_in[2];
    const float* b1      = (const float*)d_in[3];
    const float* wq_conv = (const float*)d_in[4];
    const float* wk_conv = (const float*)d_in[5];
    const float* wv_conv = (const float*)d_in[6];
    const float* wq_pw   = (const float*)d_in[7];
    const float* wk_pw   = (const float*)d_in[8];
    const float* wv_pw   = (const float*)d_in[9];
    const float* wo_pw   = (const float*)d_in[10];
    const float* g2      = (const float*)d_in[11];
    const float* b2      = (const float*)d_in[12];
    const float* w1_pw   = (const float*)d_in[13];
    const float* w2_pw   = (const float*)d_in[14];
    const float* w2_dw   = (const float*)d_in[15];

    float* out  = (float*)d_out;
    float* qk_o = out + HOUT_SIZE;

    static int smem_set = 0;
    if (!smem_set) {
        cudaFuncSetAttribute(k_gemm_mma, cudaFuncAttributeMaxDynamicSharedMemorySize,
                             8*GSTG*sizeof(__nv_bfloat16));
        smem_set = 1;
    }

    k_prep<<<4160, 256>>>(wq_pw, wk_pw, wv_pw, wo_pw);
    k_norm_conv<<<NN, 256>>>(x, g1, b1, wq_conv, wk_conv, wv_conv);
    k_gemm_mma<<<dim3(16, 2, 12), 256, 8*GSTG*sizeof(__nv_bfloat16)>>>(0);
    k_attn<<<dim3(8, NBH), 256>>>(prev_qk, qk_o);
    k_gemm_mma<<<dim3(16, 2, 4), 256, 8*GSTG*sizeof(__nv_bfloat16)>>>(1);
    k_ffn<<<NN, 256>>>(x, g2, b2, w1_pw, w2_pw, w2_dw, out);
}